// round 2
// baseline (speedup 1.0000x reference)
#include <cuda_runtime.h>
#include <cuda_bf16.h>
#include <cstdint>

#define NEGC 1e9f

// Problem constants
#define B_  32
#define T_  512     // T1 == T2
#define D_  256     // D1 == D2
#define O_  256
#define KF_ 8
#define G_  64

// ---------------- scratch (static device arrays, no allocation) ----------------
__device__ float g_R [B_ * O_ * T_];     // R_l [b][o][t]
__device__ float g_Q [B_ * O_ * T_];     // Q_l [b][o][t]
__device__ float g_Uk[KF_ * T_ * O_];    // Uk  [k][t][o]
__device__ float g_Vk[KF_ * T_ * O_];    // Vk  [k][t][o]
__device__ float g_F [B_ * T_ * T_];     // F   [b][i][j]
__device__ float g_WR[B_ * G_ * T_];     // WR  [b][g][t]
__device__ float g_WQ[B_ * G_ * T_];     // WQ  [b][g][s]
__device__ float g_d1[B_ * T_];
__device__ float g_d2[B_ * T_];
__device__ float g_g1[B_ * T_];
__device__ float g_g2[B_ * T_];
__device__ float g_pq[B_ * T_];          // pad_q (1.0 where invalid)
__device__ float g_pv[B_ * T_];          // pad_v

// ---------------- mask decode (dtype-agnostic) ----------------
// Detect the on-disk encoding of the boolean masks from the first bytes of q_mask.
// q_mask[0][0..3] are guaranteed true (len1 >= T/2). Encodings:
//   uint8 bool : bytes 01 01 01 01 ...        -> byte[1] == 1
//   bf16       : bytes 80 3F 80 3F ...        -> byte[1] == 0x3F
//   float32    : bytes 00 00 80 3F ...        -> byte[3] == 0x3F
//   int32      : bytes 01 00 00 00 ...        -> otherwise
__global__ void maskconv_kernel(const unsigned char* __restrict__ q,
                                const unsigned char* __restrict__ v,
                                float* __restrict__ pq, float* __restrict__ pv) {
    int i = blockIdx.x * blockDim.x + threadIdx.x;
    if (i >= B_ * T_) return;
    unsigned char b1 = q[1], b3 = q[3];
    int type = (b1 == 1) ? 0 : (b1 == 0x3F) ? 3 : (b3 == 0x3F) ? 2 : 1;
    bool qv, vv;
    switch (type) {
        case 0: qv = q[i] != 0;                                   vv = v[i] != 0; break;
        case 1: qv = ((const int*)q)[i] != 0;                     vv = ((const int*)v)[i] != 0; break;
        case 2: qv = ((const float*)q)[i] != 0.f;                 vv = ((const float*)v)[i] != 0.f; break;
        default: qv = ((const unsigned short*)q)[i] != 0;         vv = ((const unsigned short*)v)[i] != 0; break;
    }
    pq[i] = qv ? 0.f : 1.f;
    pv[i] = vv ? 0.f : 1.f;
}

// ---------------- Uk/Vk gather: Uk[k][m] = Uflat[m*KF + k] ----------------
__global__ void perm_kernel(const float* __restrict__ U, const float* __restrict__ V,
                            float* __restrict__ Uo, float* __restrict__ Vo) {
    int tid = blockIdx.x * blockDim.x + threadIdx.x;   // 0 .. KF*T*O-1
    if (tid >= KF_ * T_ * O_) return;
    int k = tid >> 17;           // / (T_*O_) = /131072
    int m = tid & (T_ * O_ - 1);
    Uo[tid] = U[m * KF_ + k];
    Vo[tid] = V[m * KF_ + k];
}

// ---------------- generic 64x64 tile GEMM ----------------
// C[b, m, n] = sum_k A[m,k] * Bm[b, k, n]   (A shared across batch)
// EPI: C = relu(C - NEG*pad[b,n] + bias[m])
template <bool EPI>
__global__ void gemm64_kernel(const float* __restrict__ A, const float* __restrict__ Bm,
                              float* __restrict__ C, int K, int N, int Mtot,
                              long strideB, const float* __restrict__ bias,
                              const float* __restrict__ pad) {
    int b  = blockIdx.z;
    int n0 = blockIdx.x * 64;
    int m0 = blockIdx.y * 64;
    const float* Bb = Bm + (long)b * strideB;

    __shared__ float As[16][68];   // [kk][m]
    __shared__ float Bs[16][68];   // [kk][n]

    int tid = threadIdx.x;
    int tx = tid & 15, ty = tid >> 4;
    float acc[4][4] = {};

    for (int k0 = 0; k0 < K; k0 += 16) {
        #pragma unroll
        for (int p = 0; p < 4; p++) {
            int r = (tid >> 4) + p * 16;     // 0..63 (m)
            int c = tid & 15;                // 0..15 (kk)
            As[c][r] = A[(m0 + r) * K + k0 + c];
        }
        #pragma unroll
        for (int p = 0; p < 4; p++) {
            int r = (tid >> 6) + p * 4;      // 0..15 (kk)
            int c = tid & 63;                // 0..63 (n)
            Bs[r][c] = Bb[(long)(k0 + r) * N + n0 + c];
        }
        __syncthreads();
        #pragma unroll
        for (int kk = 0; kk < 16; kk++) {
            float a[4];
            #pragma unroll
            for (int i = 0; i < 4; i++) a[i] = As[kk][ty * 4 + i];
            float4 bb = *reinterpret_cast<const float4*>(&Bs[kk][tx * 4]);
            float bv[4] = {bb.x, bb.y, bb.z, bb.w};
            #pragma unroll
            for (int i = 0; i < 4; i++)
                #pragma unroll
                for (int j = 0; j < 4; j++)
                    acc[i][j] += a[i] * bv[j];
        }
        __syncthreads();
    }

    #pragma unroll
    for (int i = 0; i < 4; i++) {
        int m = m0 + ty * 4 + i;
        #pragma unroll
        for (int j = 0; j < 4; j++) {
            int n = n0 + tx * 4 + j;
            float vv = acc[i][j];
            if (EPI) {
                vv -= NEGC * pad[b * N + n];
                vv += bias[m];
                vv = fmaxf(vv, 0.f);
            }
            C[(long)b * Mtot * N + (long)m * N + n] = vv;
        }
    }
}

// ---------------- F kernel (fused factorized bilinear) ----------------
// F[b,i,j] = sum_k (sum_o Uk[k,i,o]*R[b,o,j]) * (sum_o Vk[k,i,o]*Q[b,o,j])
__global__ void f_kernel(const float* __restrict__ Uk, const float* __restrict__ Vk,
                         const float* __restrict__ R, const float* __restrict__ Q,
                         float* __restrict__ F) {
    int b  = blockIdx.z;
    int j0 = blockIdx.x * 64;
    int i0 = blockIdx.y * 64;

    __shared__ float Us[16][68], Vs[16][68];   // [oo][i]
    __shared__ float Rs[16][68], Qs[16][68];   // [oo][j]

    int tid = threadIdx.x;
    int tx = tid & 15, ty = tid >> 4;
    float f[4][4] = {};

    const float* Rb = R + (long)b * O_ * T_;
    const float* Qb = Q + (long)b * O_ * T_;

    for (int k = 0; k < KF_; k++) {
        float a1[4][4] = {}, a2[4][4] = {};
        const float* Ukk = Uk + (long)k * T_ * O_;
        const float* Vkk = Vk + (long)k * T_ * O_;

        for (int o0 = 0; o0 < O_; o0 += 16) {
            #pragma unroll
            for (int p = 0; p < 4; p++) {
                int r = (tid >> 4) + p * 16;    // i 0..63
                int c = tid & 15;               // oo 0..15
                Us[c][r] = Ukk[(i0 + r) * O_ + o0 + c];
                Vs[c][r] = Vkk[(i0 + r) * O_ + o0 + c];
            }
            #pragma unroll
            for (int p = 0; p < 4; p++) {
                int r = (tid >> 6) + p * 4;     // oo 0..15
                int c = tid & 63;               // j 0..63
                Rs[r][c] = Rb[(o0 + r) * T_ + j0 + c];
                Qs[r][c] = Qb[(o0 + r) * T_ + j0 + c];
            }
            __syncthreads();
            #pragma unroll
            for (int oo = 0; oo < 16; oo++) {
                float u[4], vv[4];
                #pragma unroll
                for (int i = 0; i < 4; i++) { u[i] = Us[oo][ty * 4 + i]; vv[i] = Vs[oo][ty * 4 + i]; }
                float4 r4 = *reinterpret_cast<const float4*>(&Rs[oo][tx * 4]);
                float4 q4 = *reinterpret_cast<const float4*>(&Qs[oo][tx * 4]);
                float rr[4] = {r4.x, r4.y, r4.z, r4.w};
                float qq[4] = {q4.x, q4.y, q4.z, q4.w};
                #pragma unroll
                for (int i = 0; i < 4; i++)
                    #pragma unroll
                    for (int j = 0; j < 4; j++) {
                        a1[i][j] += u[i]  * rr[j];
                        a2[i][j] += vv[i] * qq[j];
                    }
            }
            __syncthreads();
        }
        #pragma unroll
        for (int i = 0; i < 4; i++)
            #pragma unroll
            for (int j = 0; j < 4; j++)
                f[i][j] += a1[i][j] * a2[i][j];
    }

    #pragma unroll
    for (int i = 0; i < 4; i++)
        #pragma unroll
        for (int j = 0; j < 4; j++)
            F[(long)b * T_ * T_ + (long)(i0 + ty * 4 + i) * T_ + j0 + tx * 4 + j] = f[i][j];
}

// ---------------- fused M + d kernel ----------------
// d[b,col] = sum_g w[g] * relu( Bias[b,g,col] + sum_i Mul[b,g,i]*F[b,i,col] ) - NEG*pad[b,col]
__global__ void md_kernel(const float* __restrict__ Bias, const float* __restrict__ Mul,
                          const float* __restrict__ F, const float* __restrict__ w,
                          const float* __restrict__ pad, float* __restrict__ d) {
    int b  = blockIdx.y;
    int c0 = blockIdx.x * 64;

    __shared__ float Ms[16][68];   // [ii][g]
    __shared__ float Fs[16][68];   // [ii][col]
    __shared__ float red[16][64];

    int tid = threadIdx.x;
    int tx = tid & 15, ty = tid >> 4;
    float acc[4][4] = {};

    const float* Mb = Mul + (long)b * G_ * T_;
    const float* Fb = F   + (long)b * T_ * T_;

    for (int i0 = 0; i0 < T_; i0 += 16) {
        #pragma unroll
        for (int p = 0; p < 4; p++) {
            int r = (tid >> 4) + p * 16;   // g 0..63
            int c = tid & 15;              // ii 0..15
            Ms[c][r] = Mb[r * T_ + i0 + c];
        }
        #pragma unroll
        for (int p = 0; p < 4; p++) {
            int r = (tid >> 6) + p * 4;    // ii
            int c = tid & 63;              // col
            Fs[r][c] = Fb[(long)(i0 + r) * T_ + c0 + c];
        }
        __syncthreads();
        #pragma unroll
        for (int ii = 0; ii < 16; ii++) {
            float m[4];
            #pragma unroll
            for (int i = 0; i < 4; i++) m[i] = Ms[ii][ty * 4 + i];
            float4 f4 = *reinterpret_cast<const float4*>(&Fs[ii][tx * 4]);
            float ff[4] = {f4.x, f4.y, f4.z, f4.w};
            #pragma unroll
            for (int i = 0; i < 4; i++)
                #pragma unroll
                for (int j = 0; j < 4; j++)
                    acc[i][j] += m[i] * ff[j];
        }
        __syncthreads();
    }

    float part[4] = {0.f, 0.f, 0.f, 0.f};
    #pragma unroll
    for (int gq = 0; gq < 4; gq++) {
        int g = ty * 4 + gq;
        float wg = w[g];
        #pragma unroll
        for (int c = 0; c < 4; c++) {
            float vv = acc[gq][c] + Bias[(long)b * G_ * T_ + g * T_ + c0 + tx * 4 + c];
            part[c] += wg * fmaxf(vv, 0.f);
        }
    }
    #pragma unroll
    for (int c = 0; c < 4; c++) red[ty][tx * 4 + c] = part[c];
    __syncthreads();
    #pragma unroll
    for (int s = 8; s > 0; s >>= 1) {
        if (ty < s) {
            #pragma unroll
            for (int c = 0; c < 4; c++) red[ty][tx * 4 + c] += red[ty + s][tx * 4 + c];
        }
        __syncthreads();
    }
    if (ty == 0) {
        #pragma unroll
        for (int c = 0; c < 4; c++) {
            int col = c0 + tx * 4 + c;
            d[b * T_ + col] = red[0][tx * 4 + c] - NEGC * pad[b * T_ + col];
        }
    }
}

// ---------------- softmax ----------------
__global__ void softmax_kernel(const float* __restrict__ d1, const float* __restrict__ d2,
                               float* __restrict__ g1, float* __restrict__ g2) {
    int b = blockIdx.x;
    const float* d = blockIdx.y ? d2 : d1;
    float* g = blockIdx.y ? g2 : g1;
    int t = threadIdx.x;   // 512 threads

    float v = d[b * T_ + t];
    __shared__ float red[16];
    float m = v;
    #pragma unroll
    for (int o = 16; o; o >>= 1) m = fmaxf(m, __shfl_xor_sync(0xffffffffu, m, o));
    if ((t & 31) == 0) red[t >> 5] = m;
    __syncthreads();
    if (t < 32) {
        float x = (t < 16) ? red[t] : -3.4e38f;
        #pragma unroll
        for (int o = 8; o; o >>= 1) x = fmaxf(x, __shfl_xor_sync(0xffffffffu, x, o));
        if (t == 0) red[0] = x;
    }
    __syncthreads();
    float mx = red[0];
    __syncthreads();

    float e = expf(v - mx);
    float s = e;
    #pragma unroll
    for (int o = 16; o; o >>= 1) s += __shfl_xor_sync(0xffffffffu, s, o);
    if ((t & 31) == 0) red[t >> 5] = s;
    __syncthreads();
    if (t < 32) {
        float x = (t < 16) ? red[t] : 0.f;
        #pragma unroll
        for (int o = 8; o; o >>= 1) x += __shfl_xor_sync(0xffffffffu, x, o);
        if (t == 0) red[0] = x;
    }
    __syncthreads();
    g[b * T_ + t] = e / red[0];
}

// ---------------- final reduction ----------------
// trace[b,o] = sum_t gv[b,t]*Rflat[b, t*O + o]; out = trace * log
__global__ void final_kernel(const float* __restrict__ R, const float* __restrict__ Q,
                             const float* __restrict__ gv, const float* __restrict__ gq,
                             float* __restrict__ out) {
    int b = blockIdx.x;
    __shared__ float sgv[T_], sgq[T_];
    int tid = threadIdx.x;   // 512
    sgv[tid] = gv[b * T_ + tid];
    sgq[tid] = gq[b * T_ + tid];
    __syncthreads();

    int o = tid & 255;
    int h = tid >> 8;
    const float* Rb = R + (long)b * O_ * T_;
    const float* Qb = Q + (long)b * O_ * T_;
    float tr = 0.f, lg = 0.f;
    #pragma unroll 4
    for (int t = h * 256; t < h * 256 + 256; t++) {
        tr += sgv[t] * Rb[t * O_ + o];
        lg += sgq[t] * Qb[t * O_ + o];
    }
    __shared__ float str[2][256], slg[2][256];
    str[h][o] = tr;
    slg[h][o] = lg;
    __syncthreads();
    if (h == 0) out[b * O_ + o] = (str[0][o] + str[1][o]) * (slg[0][o] + slg[1][o]);
}

// ---------------- launcher ----------------
extern "C" void kernel_launch(void* const* d_in, const int* in_sizes, int n_in,
                              void* d_out, int out_size) {
    const float* x0  = (const float*)d_in[0];
    const float* x1  = (const float*)d_in[1];
    const unsigned char* qm = (const unsigned char*)d_in[2];
    const unsigned char* vm = (const unsigned char*)d_in[3];
    const float* W_R = (const float*)d_in[4];
    const float* W_Q = (const float*)d_in[5];
    const float* br  = (const float*)d_in[6];
    const float* bq  = (const float*)d_in[7];
    const float* U   = (const float*)d_in[8];
    const float* V   = (const float*)d_in[9];
    const float* W2R = (const float*)d_in[10];
    const float* W2Q = (const float*)d_in[11];
    const float* wmv = (const float*)d_in[12];
    const float* wmq = (const float*)d_in[13];
    float* out = (float*)d_out;

    float *pR, *pQ, *pUk, *pVk, *pF, *pWR, *pWQ, *pd1, *pd2, *pg1, *pg2, *ppq, *ppv;
    cudaGetSymbolAddress((void**)&pR,  g_R);
    cudaGetSymbolAddress((void**)&pQ,  g_Q);
    cudaGetSymbolAddress((void**)&pUk, g_Uk);
    cudaGetSymbolAddress((void**)&pVk, g_Vk);
    cudaGetSymbolAddress((void**)&pF,  g_F);
    cudaGetSymbolAddress((void**)&pWR, g_WR);
    cudaGetSymbolAddress((void**)&pWQ, g_WQ);
    cudaGetSymbolAddress((void**)&pd1, g_d1);
    cudaGetSymbolAddress((void**)&pd2, g_d2);
    cudaGetSymbolAddress((void**)&pg1, g_g1);
    cudaGetSymbolAddress((void**)&pg2, g_g2);
    cudaGetSymbolAddress((void**)&ppq, g_pq);
    cudaGetSymbolAddress((void**)&ppv, g_pv);

    // 1. mask decode + Uk/Vk gather (independent)
    maskconv_kernel<<<(B_ * T_ + 255) / 256, 256>>>(qm, vm, ppq, ppv);
    perm_kernel<<<(KF_ * T_ * O_ + 255) / 256, 256>>>(U, V, pUk, pVk);

    // 2. R_l, Q_l GEMMs with mask/bias/relu epilogue
    gemm64_kernel<true><<<dim3(T_ / 64, O_ / 64, B_), 256>>>(
        W_R, x0, pR, D_, T_, O_, (long)D_ * T_, br, ppq);
    gemm64_kernel<true><<<dim3(T_ / 64, O_ / 64, B_), 256>>>(
        W_Q, x1, pQ, D_, T_, O_, (long)D_ * T_, bq, ppv);

    // 3. fused factorized bilinear F
    f_kernel<<<dim3(T_ / 64, T_ / 64, B_), 256>>>(pUk, pVk, pR, pQ, pF);

    // 4. WR = W2_R @ R_l ; WQ = W2_Q @ Q_l
    gemm64_kernel<false><<<dim3(T_ / 64, 1, B_), 256>>>(
        W2R, pR, pWR, O_, T_, G_, (long)O_ * T_, nullptr, nullptr);
    gemm64_kernel<false><<<dim3(T_ / 64, 1, B_), 256>>>(
        W2Q, pQ, pWQ, O_, T_, G_, (long)O_ * T_, nullptr, nullptr);

    // 5. fused M_v/M_q + relu + g-reduction -> d1, d2
    md_kernel<<<dim3(T_ / 64, B_), 256>>>(pWR, pWQ, pF, wmv, ppq, pd1);
    md_kernel<<<dim3(T_ / 64, B_), 256>>>(pWQ, pWR, pF, wmq, ppv, pd2);

    // 6. softmax -> gamma_v, gamma_q
    softmax_kernel<<<dim3(B_, 2), T_>>>(pd1, pd2, pg1, pg2);

    // 7. final weighted reductions + elementwise product
    final_kernel<<<B_, T_>>>(pR, pQ, pg1, pg2, out);
}

// round 4
// speedup vs baseline: 2.2269x; 2.2269x over previous
#include <cuda_runtime.h>
#include <cuda_bf16.h>
#include <cstdint>

#define NEGC 1e9f

#define B_  32
#define T_  512
#define D_  256
#define O_  256
#define KF_ 8
#define G_  64

// ---------------- scratch ----------------
__device__ float g_R [B_ * O_ * T_];
__device__ float g_Q [B_ * O_ * T_];
__device__ float g_F [B_ * T_ * T_];
__device__ float g_WR[B_ * G_ * T_];
__device__ float g_WQ[B_ * G_ * T_];
__device__ float g_d1[B_ * T_];
__device__ float g_d2[B_ * T_];
__device__ float g_g1[B_ * T_];
__device__ float g_g2[B_ * T_];
__device__ float g_pq[B_ * T_];
__device__ float g_pv[B_ * T_];

__device__ __nv_bfloat16 g_Ukh[KF_ * T_ * O_];
__device__ __nv_bfloat16 g_Ukl[KF_ * T_ * O_];
__device__ __nv_bfloat16 g_Vkh[KF_ * T_ * O_];
__device__ __nv_bfloat16 g_Vkl[KF_ * T_ * O_];
__device__ __nv_bfloat16 g_Rth[B_ * T_ * O_];
__device__ __nv_bfloat16 g_Rtl[B_ * T_ * O_];
__device__ __nv_bfloat16 g_Qth[B_ * T_ * O_];
__device__ __nv_bfloat16 g_Qtl[B_ * T_ * O_];

// =================== base-ISA tensor-core helpers (sm_80+) ===================
__device__ __forceinline__ uint32_t smem_to_u32(const void* p) {
    uint32_t a;
    asm("{ .reg .u64 t; cvta.to.shared.u64 t, %1; cvt.u32.u64 %0, t; }" : "=r"(a) : "l"(p));
    return a;
}
__device__ __forceinline__ void ldsm4(uint32_t* r, uint32_t addr) {
    asm volatile("ldmatrix.sync.aligned.m8n8.x4.shared.b16 {%0,%1,%2,%3}, [%4];"
        : "=r"(r[0]), "=r"(r[1]), "=r"(r[2]), "=r"(r[3]) : "r"(addr));
}
__device__ __forceinline__ void mma16816(float* d, const uint32_t* a,
                                         uint32_t b0, uint32_t b1) {
    asm volatile("mma.sync.aligned.m16n8k16.row.col.f32.bf16.bf16.f32 "
        "{%0,%1,%2,%3}, {%4,%5,%6,%7}, {%8,%9}, {%0,%1,%2,%3};"
        : "+f"(d[0]), "+f"(d[1]), "+f"(d[2]), "+f"(d[3])
        : "r"(a[0]), "r"(a[1]), "r"(a[2]), "r"(a[3]), "r"(b0), "r"(b1));
}
// swizzle for 128B rows: XOR column-16B-chunk with (row & 7)
__device__ __forceinline__ uint32_t swz(uint32_t x) {
    return x ^ (((x >> 7) & 7) << 4);
}

// ---------------- mask decode ----------------
__global__ void maskconv_kernel(const unsigned char* __restrict__ q,
                                const unsigned char* __restrict__ v,
                                float* __restrict__ pq, float* __restrict__ pv) {
    int i = blockIdx.x * blockDim.x + threadIdx.x;
    if (i >= B_ * T_) return;
    unsigned char b1 = q[1], b3 = q[3];
    int type = (b1 == 1) ? 0 : (b1 == 0x3F) ? 3 : (b3 == 0x3F) ? 2 : 1;
    bool qv, vv;
    switch (type) {
        case 0: qv = q[i] != 0;                            vv = v[i] != 0; break;
        case 1: qv = ((const int*)q)[i] != 0;              vv = ((const int*)v)[i] != 0; break;
        case 2: qv = ((const float*)q)[i] != 0.f;          vv = ((const float*)v)[i] != 0.f; break;
        default: qv = ((const unsigned short*)q)[i] != 0;  vv = ((const unsigned short*)v)[i] != 0; break;
    }
    pq[i] = qv ? 0.f : 1.f;
    pv[i] = vv ? 0.f : 1.f;
}

// ---------------- U/V de-interleave + bf16 split ----------------
__global__ void convUV_kernel(const float* __restrict__ U, const float* __restrict__ V,
                              __nv_bfloat16* __restrict__ Uh, __nv_bfloat16* __restrict__ Ul,
                              __nv_bfloat16* __restrict__ Vh, __nv_bfloat16* __restrict__ Vl) {
    int idx = blockIdx.x * blockDim.x + threadIdx.x;
    if (idx >= KF_ * T_ * O_) return;
    int k = idx >> 17;
    int m = idx & (T_ * O_ - 1);
    float u = U[m * KF_ + k];
    float v = V[m * KF_ + k];
    __nv_bfloat16 uh = __float2bfloat16(u);
    __nv_bfloat16 vh = __float2bfloat16(v);
    Uh[idx] = uh; Ul[idx] = __float2bfloat16(u - __bfloat162float(uh));
    Vh[idx] = vh; Vl[idx] = __float2bfloat16(v - __bfloat162float(vh));
}

// ---------------- transpose + bf16 split: Rt[b][t][o] = R[b][o][t] ----------------
__global__ void convRQ_kernel(const float* __restrict__ R, const float* __restrict__ Q,
                              __nv_bfloat16* __restrict__ Rh, __nv_bfloat16* __restrict__ Rl,
                              __nv_bfloat16* __restrict__ Qh, __nv_bfloat16* __restrict__ Ql) {
    __shared__ float tile[32][33];
    int zz = blockIdx.z;
    int b = zz & 31;
    bool isQ = (zz >> 5) != 0;
    const float* src = (isQ ? Q : R) + (long)b * O_ * T_;
    __nv_bfloat16* dh = (isQ ? Qh : Rh) + (long)b * T_ * O_;
    __nv_bfloat16* dl = (isQ ? Ql : Rl) + (long)b * T_ * O_;
    int t0 = blockIdx.x * 32, o0 = blockIdx.y * 32;
    int tx = threadIdx.x, ty = threadIdx.y;
    #pragma unroll
    for (int r = 0; r < 4; r++)
        tile[ty + r * 8][tx] = src[(long)(o0 + ty + r * 8) * T_ + t0 + tx];
    __syncthreads();
    #pragma unroll
    for (int r = 0; r < 4; r++) {
        int t = t0 + ty + r * 8;
        float v = tile[tx][ty + r * 8];
        __nv_bfloat16 h = __float2bfloat16(v);
        dh[(long)t * O_ + o0 + tx] = h;
        dl[(long)t * O_ + o0 + tx] = __float2bfloat16(v - __bfloat162float(h));
    }
}

// ---------------- 64x64 tile fp32 GEMM (R/Q, W2) ----------------
template <bool EPI>
__global__ void gemm64_kernel(const float* __restrict__ A, const float* __restrict__ Bm,
                              float* __restrict__ C, int K, int N, int Mtot,
                              long strideB, const float* __restrict__ bias,
                              const float* __restrict__ pad) {
    int b  = blockIdx.z;
    int n0 = blockIdx.x * 64;
    int m0 = blockIdx.y * 64;
    const float* Bb = Bm + (long)b * strideB;
    __shared__ float As[16][68];
    __shared__ float Bs[16][68];
    int tid = threadIdx.x;
    int tx = tid & 15, ty = tid >> 4;
    float acc[4][4] = {};
    for (int k0 = 0; k0 < K; k0 += 16) {
        #pragma unroll
        for (int p = 0; p < 4; p++) {
            int r = (tid >> 4) + p * 16;
            int c = tid & 15;
            As[c][r] = A[(m0 + r) * K + k0 + c];
        }
        #pragma unroll
        for (int p = 0; p < 4; p++) {
            int r = (tid >> 6) + p * 4;
            int c = tid & 63;
            Bs[r][c] = Bb[(long)(k0 + r) * N + n0 + c];
        }
        __syncthreads();
        #pragma unroll
        for (int kk = 0; kk < 16; kk++) {
            float a[4];
            #pragma unroll
            for (int i = 0; i < 4; i++) a[i] = As[kk][ty * 4 + i];
            float4 bb = *reinterpret_cast<const float4*>(&Bs[kk][tx * 4]);
            float bv[4] = {bb.x, bb.y, bb.z, bb.w};
            #pragma unroll
            for (int i = 0; i < 4; i++)
                #pragma unroll
                for (int j = 0; j < 4; j++)
                    acc[i][j] += a[i] * bv[j];
        }
        __syncthreads();
    }
    #pragma unroll
    for (int i = 0; i < 4; i++) {
        int m = m0 + ty * 4 + i;
        #pragma unroll
        for (int j = 0; j < 4; j++) {
            int n = n0 + tx * 4 + j;
            float vv = acc[i][j];
            if (EPI) {
                vv -= NEGC * pad[b * N + n];
                vv += bias[m];
                vv = fmaxf(vv, 0.f);
            }
            C[(long)b * Mtot * N + (long)m * N + n] = vv;
        }
    }
}

// ======================= HMMA (mma.sync) F kernel =======================
// F[b,i,j] = sum_k dot1_k[i,j]*dot2_k[i,j]
// dot1 = U_k[i,:] . Rt[j,:], dot2 = V_k[i,:] . Qt[j,:]  (split bf16, 3 terms)
// CTA: i-tile 128, j-tile 64, one b. 8 warps, warp tile 32x32 (wi=w>>1, wj=w&1).
// SMEM: A buffer 4 arrays x [128i][64o] bf16 (16KB each) at 0;
//       B persistent 4 arrays x 4 oc x [64j][64o] (8KB tiles) at 65536. Total 192KB.
#define FS_B 65536
#define FS_TOTAL 196608

__global__ __launch_bounds__(256, 1) void f_mma_kernel(
    const __nv_bfloat16* __restrict__ Uh, const __nv_bfloat16* __restrict__ Ul,
    const __nv_bfloat16* __restrict__ Vh, const __nv_bfloat16* __restrict__ Vl,
    const __nv_bfloat16* __restrict__ Rh, const __nv_bfloat16* __restrict__ Rl,
    const __nv_bfloat16* __restrict__ Qh, const __nv_bfloat16* __restrict__ Ql,
    float* __restrict__ F) {
    extern __shared__ char sm[];
    uint32_t sb = smem_to_u32(sm);
    int tid = threadIdx.x, lane = tid & 31, w = tid >> 5;
    int wi = w >> 1, wj = w & 1;
    int b = blockIdx.z, i0 = blockIdx.y * 128, j0 = blockIdx.x * 64;
    int l16 = lane & 15, lh = lane >> 4;

    // ---- load persistent B: 4 arrays x [64j][256o] ----
    {
        const __nv_bfloat16* bp[4] = {Rh, Rl, Qh, Ql};
        #pragma unroll
        for (int arr = 0; arr < 4; arr++) {
            const __nv_bfloat16* src = bp[arr] + ((long)b * T_ + j0) * O_;
            #pragma unroll
            for (int e = 0; e < 8; e++) {
                int idx = tid + e * 256;          // 0..2047
                int row = idx >> 5, qc = idx & 31;
                uint4 v = *reinterpret_cast<const uint4*>(src + (long)row * O_ + qc * 8);
                uint32_t off = (uint32_t)((qc >> 3) * 8192) + swz((uint32_t)(row * 128 + (qc & 7) * 16));
                *reinterpret_cast<uint4*>(sm + FS_B + arr * 32768 + off) = v;
            }
        }
    }

    const __nv_bfloat16* apt[4] = {Uh, Ul, Vh, Vl};

    float f[32];
    #pragma unroll
    for (int i = 0; i < 32; i++) f[i] = 0.f;

    for (int k = 0; k < KF_; k++) {
        float d1[32], d2[32];
        #pragma unroll
        for (int i = 0; i < 32; i++) { d1[i] = 0.f; d2[i] = 0.f; }

        for (int oc = 0; oc < 4; oc++) {
            __syncthreads();
            // load A chunk: 4 arrays x [128i][64o]
            #pragma unroll
            for (int arr = 0; arr < 4; arr++) {
                const __nv_bfloat16* src = apt[arr] + ((long)k * T_ + i0) * O_ + oc * 64;
                #pragma unroll
                for (int e = 0; e < 4; e++) {
                    int idx = tid + e * 256;      // 0..1023
                    int row = idx >> 3, c = idx & 7;
                    uint4 v = *reinterpret_cast<const uint4*>(src + (long)row * O_ + c * 8);
                    uint32_t off = swz((uint32_t)(row * 128 + c * 16));
                    *reinterpret_cast<uint4*>(sm + arr * 16384 + off) = v;
                }
            }
            __syncthreads();

            #pragma unroll
            for (int os = 0; os < 4; os++) {
                uint32_t colb = (uint32_t)(os * 32 + lh * 16);
                uint32_t arow = (uint32_t)(wi * 32 + l16);
                uint32_t brow = (uint32_t)(wj * 32 + l16);

                // ---- pass 1: d1 += U . R  (3 split terms) ----
                {
                    uint32_t ah0[4], ah1[4], al0[4], al1[4];
                    ldsm4(ah0, sb + 0 * 16384 + swz(arow * 128 + colb));
                    ldsm4(ah1, sb + 0 * 16384 + swz((arow + 16) * 128 + colb));
                    ldsm4(al0, sb + 1 * 16384 + swz(arow * 128 + colb));
                    ldsm4(al1, sb + 1 * 16384 + swz((arow + 16) * 128 + colb));
                    uint32_t bh0[4], bh1[4], bl0[4], bl1[4];
                    uint32_t bbase0 = sb + FS_B + 0 * 32768 + oc * 8192;
                    uint32_t bbase1 = sb + FS_B + 1 * 32768 + oc * 8192;
                    ldsm4(bh0, bbase0 + swz(brow * 128 + colb));
                    ldsm4(bh1, bbase0 + swz((brow + 16) * 128 + colb));
                    ldsm4(bl0, bbase1 + swz(brow * 128 + colb));
                    ldsm4(bl1, bbase1 + swz((brow + 16) * 128 + colb));
                    #pragma unroll
                    for (int mt = 0; mt < 2; mt++) {
                        const uint32_t* ah = mt ? ah1 : ah0;
                        const uint32_t* al = mt ? al1 : al0;
                        #pragma unroll
                        for (int nt = 0; nt < 4; nt++) {
                            const uint32_t* bh = (nt >> 1) ? bh1 : bh0;
                            const uint32_t* bl = (nt >> 1) ? bl1 : bl0;
                            int s = nt & 1;
                            float* d = d1 + (mt * 4 + nt) * 4;
                            mma16816(d, ah, bh[s], bh[s + 2]);
                            mma16816(d, ah, bl[s], bl[s + 2]);
                            mma16816(d, al, bh[s], bh[s + 2]);
                        }
                    }
                }
                // ---- pass 2: d2 += V . Q ----
                {
                    uint32_t ah0[4], ah1[4], al0[4], al1[4];
                    ldsm4(ah0, sb + 2 * 16384 + swz(arow * 128 + colb));
                    ldsm4(ah1, sb + 2 * 16384 + swz((arow + 16) * 128 + colb));
                    ldsm4(al0, sb + 3 * 16384 + swz(arow * 128 + colb));
                    ldsm4(al1, sb + 3 * 16384 + swz((arow + 16) * 128 + colb));
                    uint32_t bh0[4], bh1[4], bl0[4], bl1[4];
                    uint32_t bbase2 = sb + FS_B + 2 * 32768 + oc * 8192;
                    uint32_t bbase3 = sb + FS_B + 3 * 32768 + oc * 8192;
                    ldsm4(bh0, bbase2 + swz(brow * 128 + colb));
                    ldsm4(bh1, bbase2 + swz((brow + 16) * 128 + colb));
                    ldsm4(bl0, bbase3 + swz(brow * 128 + colb));
                    ldsm4(bl1, bbase3 + swz((brow + 16) * 128 + colb));
                    #pragma unroll
                    for (int mt = 0; mt < 2; mt++) {
                        const uint32_t* ah = mt ? ah1 : ah0;
                        const uint32_t* al = mt ? al1 : al0;
                        #pragma unroll
                        for (int nt = 0; nt < 4; nt++) {
                            const uint32_t* bh = (nt >> 1) ? bh1 : bh0;
                            const uint32_t* bl = (nt >> 1) ? bl1 : bl0;
                            int s = nt & 1;
                            float* d = d2 + (mt * 4 + nt) * 4;
                            mma16816(d, ah, bh[s], bh[s + 2]);
                            mma16816(d, ah, bl[s], bl[s + 2]);
                            mma16816(d, al, bh[s], bh[s + 2]);
                        }
                    }
                }
            }
        }
        #pragma unroll
        for (int i = 0; i < 32; i++) f[i] += d1[i] * d2[i];
    }

    // ---- epilogue: write F tile ----
    int r4 = lane >> 2, c2 = (lane & 3) * 2;
    #pragma unroll
    for (int mt = 0; mt < 2; mt++) {
        #pragma unroll
        for (int nt = 0; nt < 4; nt++) {
            float* d = f + (mt * 4 + nt) * 4;
            long row = i0 + wi * 32 + mt * 16 + r4;
            long col = j0 + wj * 32 + nt * 8 + c2;
            float* dst = F + ((long)b * T_ + row) * T_ + col;
            dst[0] = d[0]; dst[1] = d[1];
            dst[8 * T_] = d[2]; dst[8 * T_ + 1] = d[3];
        }
    }
}

// ---------------- fused M + d kernel ----------------
__global__ void md_kernel(const float* __restrict__ Bias, const float* __restrict__ Mul,
                          const float* __restrict__ F, const float* __restrict__ w,
                          const float* __restrict__ pad, float* __restrict__ d) {
    int b  = blockIdx.y;
    int c0 = blockIdx.x * 64;
    __shared__ float Ms[16][68];
    __shared__ float Fs[16][68];
    __shared__ float red[16][64];
    int tid = threadIdx.x;
    int tx = tid & 15, ty = tid >> 4;
    float acc[4][4] = {};
    const float* Mb = Mul + (long)b * G_ * T_;
    const float* Fb = F   + (long)b * T_ * T_;
    for (int i0 = 0; i0 < T_; i0 += 16) {
        #pragma unroll
        for (int p = 0; p < 4; p++) {
            int r = (tid >> 4) + p * 16;
            int c = tid & 15;
            Ms[c][r] = Mb[r * T_ + i0 + c];
        }
        #pragma unroll
        for (int p = 0; p < 4; p++) {
            int r = (tid >> 6) + p * 4;
            int c = tid & 63;
            Fs[r][c] = Fb[(long)(i0 + r) * T_ + c0 + c];
        }
        __syncthreads();
        #pragma unroll
        for (int ii = 0; ii < 16; ii++) {
            float m[4];
            #pragma unroll
            for (int i = 0; i < 4; i++) m[i] = Ms[ii][ty * 4 + i];
            float4 f4 = *reinterpret_cast<const float4*>(&Fs[ii][tx * 4]);
            float ff[4] = {f4.x, f4.y, f4.z, f4.w};
            #pragma unroll
            for (int i = 0; i < 4; i++)
                #pragma unroll
                for (int j = 0; j < 4; j++)
                    acc[i][j] += m[i] * ff[j];
        }
        __syncthreads();
    }
    float part[4] = {0.f, 0.f, 0.f, 0.f};
    #pragma unroll
    for (int gq = 0; gq < 4; gq++) {
        int g = ty * 4 + gq;
        float wg = w[g];
        #pragma unroll
        for (int c = 0; c < 4; c++) {
            float vv = acc[gq][c] + Bias[(long)b * G_ * T_ + g * T_ + c0 + tx * 4 + c];
            part[c] += wg * fmaxf(vv, 0.f);
        }
    }
    #pragma unroll
    for (int c = 0; c < 4; c++) red[ty][tx * 4 + c] = part[c];
    __syncthreads();
    #pragma unroll
    for (int s = 8; s > 0; s >>= 1) {
        if (ty < s) {
            #pragma unroll
            for (int c = 0; c < 4; c++) red[ty][tx * 4 + c] += red[ty + s][tx * 4 + c];
        }
        __syncthreads();
    }
    if (ty == 0) {
        #pragma unroll
        for (int c = 0; c < 4; c++) {
            int col = c0 + tx * 4 + c;
            d[b * T_ + col] = red[0][tx * 4 + c] - NEGC * pad[b * T_ + col];
        }
    }
}

// ---------------- softmax ----------------
__global__ void softmax_kernel(const float* __restrict__ d1, const float* __restrict__ d2,
                               float* __restrict__ g1, float* __restrict__ g2) {
    int b = blockIdx.x;
    const float* d = blockIdx.y ? d2 : d1;
    float* g = blockIdx.y ? g2 : g1;
    int t = threadIdx.x;
    float v = d[b * T_ + t];
    __shared__ float red[16];
    float m = v;
    #pragma unroll
    for (int o = 16; o; o >>= 1) m = fmaxf(m, __shfl_xor_sync(0xffffffffu, m, o));
    if ((t & 31) == 0) red[t >> 5] = m;
    __syncthreads();
    if (t < 32) {
        float x = (t < 16) ? red[t] : -3.4e38f;
        #pragma unroll
        for (int o = 8; o; o >>= 1) x = fmaxf(x, __shfl_xor_sync(0xffffffffu, x, o));
        if (t == 0) red[0] = x;
    }
    __syncthreads();
    float mx = red[0];
    __syncthreads();
    float e = expf(v - mx);
    float s = e;
    #pragma unroll
    for (int o = 16; o; o >>= 1) s += __shfl_xor_sync(0xffffffffu, s, o);
    if ((t & 31) == 0) red[t >> 5] = s;
    __syncthreads();
    if (t < 32) {
        float x = (t < 16) ? red[t] : 0.f;
        #pragma unroll
        for (int o = 8; o; o >>= 1) x += __shfl_xor_sync(0xffffffffu, x, o);
        if (t == 0) red[0] = x;
    }
    __syncthreads();
    g[b * T_ + t] = e / red[0];
}

// ---------------- final reduction ----------------
__global__ void final_kernel(const float* __restrict__ R, const float* __restrict__ Q,
                             const float* __restrict__ gv, const float* __restrict__ gq,
                             float* __restrict__ out) {
    int b = blockIdx.x;
    __shared__ float sgv[T_], sgq[T_];
    int tid = threadIdx.x;
    sgv[tid] = gv[b * T_ + tid];
    sgq[tid] = gq[b * T_ + tid];
    __syncthreads();
    int o = tid & 255;
    int h = tid >> 8;
    const float* Rb = R + (long)b * O_ * T_;
    const float* Qb = Q + (long)b * O_ * T_;
    float tr = 0.f, lg = 0.f;
    #pragma unroll 4
    for (int t = h * 256; t < h * 256 + 256; t++) {
        tr += sgv[t] * Rb[t * O_ + o];
        lg += sgq[t] * Qb[t * O_ + o];
    }
    __shared__ float str[2][256], slg[2][256];
    str[h][o] = tr;
    slg[h][o] = lg;
    __syncthreads();
    if (h == 0) out[b * O_ + o] = (str[0][o] + str[1][o]) * (slg[0][o] + slg[1][o]);
}

// ---------------- launcher ----------------
extern "C" void kernel_launch(void* const* d_in, const int* in_sizes, int n_in,
                              void* d_out, int out_size) {
    const float* x0  = (const float*)d_in[0];
    const float* x1  = (const float*)d_in[1];
    const unsigned char* qm = (const unsigned char*)d_in[2];
    const unsigned char* vm = (const unsigned char*)d_in[3];
    const float* W_R = (const float*)d_in[4];
    const float* W_Q = (const float*)d_in[5];
    const float* br  = (const float*)d_in[6];
    const float* bq  = (const float*)d_in[7];
    const float* U   = (const float*)d_in[8];
    const float* V   = (const float*)d_in[9];
    const float* W2R = (const float*)d_in[10];
    const float* W2Q = (const float*)d_in[11];
    const float* wmv = (const float*)d_in[12];
    const float* wmq = (const float*)d_in[13];
    float* out = (float*)d_out;

    float *pR, *pQ, *pF, *pWR, *pWQ, *pd1, *pd2, *pg1, *pg2, *ppq, *ppv;
    __nv_bfloat16 *pUh, *pUl, *pVh, *pVl, *pRh, *pRl, *pQh, *pQl;
    cudaGetSymbolAddress((void**)&pR,  g_R);
    cudaGetSymbolAddress((void**)&pQ,  g_Q);
    cudaGetSymbolAddress((void**)&pF,  g_F);
    cudaGetSymbolAddress((void**)&pWR, g_WR);
    cudaGetSymbolAddress((void**)&pWQ, g_WQ);
    cudaGetSymbolAddress((void**)&pd1, g_d1);
    cudaGetSymbolAddress((void**)&pd2, g_d2);
    cudaGetSymbolAddress((void**)&pg1, g_g1);
    cudaGetSymbolAddress((void**)&pg2, g_g2);
    cudaGetSymbolAddress((void**)&ppq, g_pq);
    cudaGetSymbolAddress((void**)&ppv, g_pv);
    cudaGetSymbolAddress((void**)&pUh, g_Ukh);
    cudaGetSymbolAddress((void**)&pUl, g_Ukl);
    cudaGetSymbolAddress((void**)&pVh, g_Vkh);
    cudaGetSymbolAddress((void**)&pVl, g_Vkl);
    cudaGetSymbolAddress((void**)&pRh, g_Rth);
    cudaGetSymbolAddress((void**)&pRl, g_Rtl);
    cudaGetSymbolAddress((void**)&pQh, g_Qth);
    cudaGetSymbolAddress((void**)&pQl, g_Qtl);

    static bool attr_done = false;
    if (!attr_done) {
        cudaFuncSetAttribute(f_mma_kernel, cudaFuncAttributeMaxDynamicSharedMemorySize, FS_TOTAL);
        attr_done = true;
    }

    // 1. mask decode + U/V split (independent)
    maskconv_kernel<<<(B_ * T_ + 255) / 256, 256>>>(qm, vm, ppq, ppv);
    convUV_kernel<<<(KF_ * T_ * O_ + 255) / 256, 256>>>(U, V, pUh, pUl, pVh, pVl);

    // 2. R_l, Q_l GEMMs with mask/bias/relu epilogue
    gemm64_kernel<true><<<dim3(T_ / 64, O_ / 64, B_), 256>>>(
        W_R, x0, pR, D_, T_, O_, (long)D_ * T_, br, ppq);
    gemm64_kernel<true><<<dim3(T_ / 64, O_ / 64, B_), 256>>>(
        W_Q, x1, pQ, D_, T_, O_, (long)D_ * T_, bq, ppv);

    // 3. transpose+split R/Q for tensor cores
    convRQ_kernel<<<dim3(T_ / 32, O_ / 32, 2 * B_), dim3(32, 8)>>>(
        pR, pQ, pRh, pRl, pQh, pQl);

    // 4. HMMA factorized-bilinear F
    f_mma_kernel<<<dim3(T_ / 64, T_ / 128, B_), 256, FS_TOTAL>>>(
        pUh, pUl, pVh, pVl, pRh, pRl, pQh, pQl, pF);

    // 5. W2 GEMMs
    gemm64_kernel<false><<<dim3(T_ / 64, 1, B_), 256>>>(
        W2R, pR, pWR, O_, T_, G_, (long)O_ * T_, nullptr, nullptr);
    gemm64_kernel<false><<<dim3(T_ / 64, 1, B_), 256>>>(
        W2Q, pQ, pWQ, O_, T_, G_, (long)O_ * T_, nullptr, nullptr);

    // 6. fused M + reduction -> d1, d2
    md_kernel<<<dim3(T_ / 64, B_), 256>>>(pWR, pWQ, pF, wmv, ppq, pd1);
    md_kernel<<<dim3(T_ / 64, B_), 256>>>(pWQ, pWR, pF, wmq, ppv, pd2);

    // 7. softmax
    softmax_kernel<<<dim3(B_, 2), T_>>>(pd1, pd2, pg1, pg2);

    // 8. final
    final_kernel<<<B_, T_>>>(pR, pQ, pg1, pg2, out);
}

// round 5
// speedup vs baseline: 2.2910x; 1.0288x over previous
#include <cuda_runtime.h>
#include <cuda_bf16.h>
#include <cstdint>

#define NEGC 1e9f

#define B_  32
#define T_  512
#define D_  256
#define O_  256
#define KF_ 8
#define G_  64

// ---------------- scratch ----------------
__device__ float g_R [B_ * O_ * T_];
__device__ float g_Q [B_ * O_ * T_];
__device__ float g_F [B_ * T_ * T_];
__device__ float g_WR[B_ * G_ * T_];
__device__ float g_WQ[B_ * G_ * T_];
__device__ float g_d1[B_ * T_];
__device__ float g_d2[B_ * T_];
__device__ float g_g1[B_ * T_];
__device__ float g_g2[B_ * T_];
__device__ float g_pq[B_ * T_];
__device__ float g_pv[B_ * T_];

__device__ __nv_bfloat16 g_Ukh[KF_ * T_ * O_];
__device__ __nv_bfloat16 g_Ukl[KF_ * T_ * O_];
__device__ __nv_bfloat16 g_Vkh[KF_ * T_ * O_];
__device__ __nv_bfloat16 g_Vkl[KF_ * T_ * O_];
__device__ __nv_bfloat16 g_Rth[B_ * T_ * O_];
__device__ __nv_bfloat16 g_Rtl[B_ * T_ * O_];
__device__ __nv_bfloat16 g_Qth[B_ * T_ * O_];
__device__ __nv_bfloat16 g_Qtl[B_ * T_ * O_];

// =================== base-ISA tensor-core helpers (sm_80+) ===================
__device__ __forceinline__ uint32_t smem_to_u32(const void* p) {
    uint32_t a;
    asm("{ .reg .u64 t; cvta.to.shared.u64 t, %1; cvt.u32.u64 %0, t; }" : "=r"(a) : "l"(p));
    return a;
}
__device__ __forceinline__ void ldsm4(uint32_t* r, uint32_t addr) {
    asm volatile("ldmatrix.sync.aligned.m8n8.x4.shared.b16 {%0,%1,%2,%3}, [%4];"
        : "=r"(r[0]), "=r"(r[1]), "=r"(r[2]), "=r"(r[3]) : "r"(addr));
}
__device__ __forceinline__ void mma16816(float* d, const uint32_t* a,
                                         uint32_t b0, uint32_t b1) {
    asm volatile("mma.sync.aligned.m16n8k16.row.col.f32.bf16.bf16.f32 "
        "{%0,%1,%2,%3}, {%4,%5,%6,%7}, {%8,%9}, {%0,%1,%2,%3};"
        : "+f"(d[0]), "+f"(d[1]), "+f"(d[2]), "+f"(d[3])
        : "r"(a[0]), "r"(a[1]), "r"(a[2]), "r"(a[3]), "r"(b0), "r"(b1));
}
__device__ __forceinline__ void cpasync16(uint32_t dst, const void* src) {
    asm volatile("cp.async.cg.shared.global [%0], [%1], 16;" :: "r"(dst), "l"(src));
}
#define CP_COMMIT() asm volatile("cp.async.commit_group;" ::: "memory")
#define CP_WAIT(n)  asm volatile("cp.async.wait_group %0;" :: "n"(n) : "memory")

// packed layout: 2 logical 64B rows per 128B physical row, XOR swizzle.
// row: logical row index; cb: byte column 0..63 (16B granular)
__device__ __forceinline__ uint32_t paddr(uint32_t row, uint32_t cb) {
    uint32_t pr = row >> 1;
    return pr * 128 + ((((row & 1) << 6) + cb) ^ ((pr & 7) << 4));
}

// ---------------- mask decode ----------------
__global__ void maskconv_kernel(const unsigned char* __restrict__ q,
                                const unsigned char* __restrict__ v,
                                float* __restrict__ pq, float* __restrict__ pv) {
    int i = blockIdx.x * blockDim.x + threadIdx.x;
    if (i >= B_ * T_) return;
    unsigned char b1 = q[1], b3 = q[3];
    int type = (b1 == 1) ? 0 : (b1 == 0x3F) ? 3 : (b3 == 0x3F) ? 2 : 1;
    bool qv, vv;
    switch (type) {
        case 0: qv = q[i] != 0;                            vv = v[i] != 0; break;
        case 1: qv = ((const int*)q)[i] != 0;              vv = ((const int*)v)[i] != 0; break;
        case 2: qv = ((const float*)q)[i] != 0.f;          vv = ((const float*)v)[i] != 0.f; break;
        default: qv = ((const unsigned short*)q)[i] != 0;  vv = ((const unsigned short*)v)[i] != 0; break;
    }
    pq[i] = qv ? 0.f : 1.f;
    pv[i] = vv ? 0.f : 1.f;
}

// ---------------- U/V de-interleave + bf16 split ----------------
__global__ void convUV_kernel(const float* __restrict__ U, const float* __restrict__ V,
                              __nv_bfloat16* __restrict__ Uh, __nv_bfloat16* __restrict__ Ul,
                              __nv_bfloat16* __restrict__ Vh, __nv_bfloat16* __restrict__ Vl) {
    int idx = blockIdx.x * blockDim.x + threadIdx.x;
    if (idx >= KF_ * T_ * O_) return;
    int k = idx >> 17;
    int m = idx & (T_ * O_ - 1);
    float u = U[m * KF_ + k];
    float v = V[m * KF_ + k];
    __nv_bfloat16 uh = __float2bfloat16(u);
    __nv_bfloat16 vh = __float2bfloat16(v);
    Uh[idx] = uh; Ul[idx] = __float2bfloat16(u - __bfloat162float(uh));
    Vh[idx] = vh; Vl[idx] = __float2bfloat16(v - __bfloat162float(vh));
}

// ---------------- transpose + bf16 split ----------------
__global__ void convRQ_kernel(const float* __restrict__ R, const float* __restrict__ Q,
                              __nv_bfloat16* __restrict__ Rh, __nv_bfloat16* __restrict__ Rl,
                              __nv_bfloat16* __restrict__ Qh, __nv_bfloat16* __restrict__ Ql) {
    __shared__ float tile[32][33];
    int zz = blockIdx.z;
    int b = zz & 31;
    bool isQ = (zz >> 5) != 0;
    const float* src = (isQ ? Q : R) + (long)b * O_ * T_;
    __nv_bfloat16* dh = (isQ ? Qh : Rh) + (long)b * T_ * O_;
    __nv_bfloat16* dl = (isQ ? Ql : Rl) + (long)b * T_ * O_;
    int t0 = blockIdx.x * 32, o0 = blockIdx.y * 32;
    int tx = threadIdx.x, ty = threadIdx.y;
    #pragma unroll
    for (int r = 0; r < 4; r++)
        tile[ty + r * 8][tx] = src[(long)(o0 + ty + r * 8) * T_ + t0 + tx];
    __syncthreads();
    #pragma unroll
    for (int r = 0; r < 4; r++) {
        int t = t0 + ty + r * 8;
        float v = tile[tx][ty + r * 8];
        __nv_bfloat16 h = __float2bfloat16(v);
        dh[(long)t * O_ + o0 + tx] = h;
        dl[(long)t * O_ + o0 + tx] = __float2bfloat16(v - __bfloat162float(h));
    }
}

// ---------------- 64x64 tile fp32 GEMM ----------------
template <bool EPI>
__global__ void gemm64_kernel(const float* __restrict__ A, const float* __restrict__ Bm,
                              float* __restrict__ C, int K, int N, int Mtot,
                              long strideB, const float* __restrict__ bias,
                              const float* __restrict__ pad) {
    int b  = blockIdx.z;
    int n0 = blockIdx.x * 64;
    int m0 = blockIdx.y * 64;
    const float* Bb = Bm + (long)b * strideB;
    __shared__ float As[16][68];
    __shared__ float Bs[16][68];
    int tid = threadIdx.x;
    int tx = tid & 15, ty = tid >> 4;
    float acc[4][4] = {};
    for (int k0 = 0; k0 < K; k0 += 16) {
        #pragma unroll
        for (int p = 0; p < 4; p++) {
            int r = (tid >> 4) + p * 16;
            int c = tid & 15;
            As[c][r] = A[(m0 + r) * K + k0 + c];
        }
        #pragma unroll
        for (int p = 0; p < 4; p++) {
            int r = (tid >> 6) + p * 4;
            int c = tid & 63;
            Bs[r][c] = Bb[(long)(k0 + r) * N + n0 + c];
        }
        __syncthreads();
        #pragma unroll
        for (int kk = 0; kk < 16; kk++) {
            float4 a4 = *reinterpret_cast<const float4*>(&As[kk][ty * 4]);
            float a[4] = {a4.x, a4.y, a4.z, a4.w};
            float4 bb = *reinterpret_cast<const float4*>(&Bs[kk][tx * 4]);
            float bv[4] = {bb.x, bb.y, bb.z, bb.w};
            #pragma unroll
            for (int i = 0; i < 4; i++)
                #pragma unroll
                for (int j = 0; j < 4; j++)
                    acc[i][j] += a[i] * bv[j];
        }
        __syncthreads();
    }
    #pragma unroll
    for (int i = 0; i < 4; i++) {
        int m = m0 + ty * 4 + i;
        #pragma unroll
        for (int j = 0; j < 4; j++) {
            int n = n0 + tx * 4 + j;
            float vv = acc[i][j];
            if (EPI) {
                vv -= NEGC * pad[b * N + n];
                vv += bias[m];
                vv = fmaxf(vv, 0.f);
            }
            C[(long)b * Mtot * N + (long)m * N + n] = vv;
        }
    }
}

// ======================= HMMA F kernel with cp.async pipeline =======================
// F[b,i,j] = sum_k dot1_k[i,j]*dot2_k[i,j]; split-bf16 3-term MMAs.
// CTA: i-tile 128, j-tile 64, one b. 8 warps (wi=w>>1 0..3, wj=w&1).
// A streamed in 32-o chunks (cu = k*8+ch), 2-stage cp.async double buffer.
// SMEM: A 2 stages x 4 arr x 8KB = 64KB at 0; B persistent 4 arr x 8 ch x 4KB = 128KB at 65536.
#define FS_B 65536
#define FS_TOTAL 196608

__global__ __launch_bounds__(256, 1) void f_mma_kernel(
    const __nv_bfloat16* __restrict__ Uh, const __nv_bfloat16* __restrict__ Ul,
    const __nv_bfloat16* __restrict__ Vh, const __nv_bfloat16* __restrict__ Vl,
    const __nv_bfloat16* __restrict__ Rh, const __nv_bfloat16* __restrict__ Rl,
    const __nv_bfloat16* __restrict__ Qh, const __nv_bfloat16* __restrict__ Ql,
    float* __restrict__ F) {
    extern __shared__ char sm[];
    uint32_t sb = smem_to_u32(sm);
    int tid = threadIdx.x, lane = tid & 31, w = tid >> 5;
    int wi = w >> 1, wj = w & 1;
    int b = blockIdx.z, i0 = blockIdx.y * 128, j0 = blockIdx.x * 64;
    int l16 = lane & 15, lh = lane >> 4;

    const __nv_bfloat16* apt[4] = {Uh, Ul, Vh, Vl};
    const __nv_bfloat16* bpt[4] = {Rh, Rl, Qh, Ql};

    // ---- B persistent via cp.async: 4 arr x [64j][256o] packed, chunked per 32 o ----
    #pragma unroll
    for (int arr = 0; arr < 4; arr++) {
        const __nv_bfloat16* src = bpt[arr] + ((long)b * T_ + j0) * O_;
        #pragma unroll
        for (int e = 0; e < 8; e++) {
            int idx = tid + e * 256;              // 0..2047 transfers of 16B
            int ch = idx >> 8;                    // 0..7
            int row = (idx & 255) >> 2;           // 0..63 (j)
            int cb = (idx & 3) * 16;              // byte col in 64B
            const void* g = src + (long)row * O_ + ch * 32 + cb / 2;
            cpasync16(sb + FS_B + arr * 32768 + ch * 4096 + paddr(row, cb), g);
        }
    }
    CP_COMMIT();

    // ---- A chunk prefetch helper (lambda-free) ----
    // chunk cu: k = cu>>3, ch = cu&7; 4 arr x [128i][32o] packed = 32KB
    // per thread: 2 transfers per array
    auto load_a = [&](int cu, int st) {
        int k = cu >> 3, ch = cu & 7;
        #pragma unroll
        for (int arr = 0; arr < 4; arr++) {
            const __nv_bfloat16* src = apt[arr] + ((long)k * T_ + i0) * O_ + ch * 32;
            #pragma unroll
            for (int e = 0; e < 2; e++) {
                int idx = tid + e * 256;          // 0..511
                int row = idx >> 2;               // 0..127 (i)
                int cb = (idx & 3) * 16;
                const void* g = src + (long)row * O_ + cb / 2;
                cpasync16(sb + st * 32768 + arr * 8192 + paddr(row, cb), g);
            }
        }
    };

    load_a(0, 0);
    CP_COMMIT();

    float f[32], d1[32], d2[32];
    #pragma unroll
    for (int i = 0; i < 32; i++) { f[i] = 0.f; d1[i] = 0.f; d2[i] = 0.f; }

    for (int cu = 0; cu < 64; cu++) {
        int st = cu & 1, ch = cu & 7;
        if (cu + 1 < 64) {
            load_a(cu + 1, (cu + 1) & 1);
            CP_COMMIT();
            CP_WAIT(1);
        } else {
            CP_WAIT(0);
        }
        __syncthreads();

        uint32_t abase = sb + st * 32768;
        #pragma unroll
        for (int os = 0; os < 2; os++) {
            uint32_t colb = (uint32_t)(os * 32 + lh * 16);
            uint32_t arow = (uint32_t)(wi * 32 + l16);
            uint32_t brow = (uint32_t)(wj * 32 + l16);

            // pass 1: d1 += U.R (hh, hl, lh)
            {
                uint32_t ah0[4], ah1[4], al0[4], al1[4];
                ldsm4(ah0, abase + 0 * 8192 + paddr(arow, colb));
                ldsm4(ah1, abase + 0 * 8192 + paddr(arow + 16, colb));
                ldsm4(al0, abase + 1 * 8192 + paddr(arow, colb));
                ldsm4(al1, abase + 1 * 8192 + paddr(arow + 16, colb));
                uint32_t bh0[4], bh1[4], bl0[4], bl1[4];
                uint32_t b0 = sb + FS_B + 0 * 32768 + ch * 4096;
                uint32_t b1 = sb + FS_B + 1 * 32768 + ch * 4096;
                ldsm4(bh0, b0 + paddr(brow, colb));
                ldsm4(bh1, b0 + paddr(brow + 16, colb));
                ldsm4(bl0, b1 + paddr(brow, colb));
                ldsm4(bl1, b1 + paddr(brow + 16, colb));
                #pragma unroll
                for (int mt = 0; mt < 2; mt++) {
                    const uint32_t* ah = mt ? ah1 : ah0;
                    const uint32_t* al = mt ? al1 : al0;
                    #pragma unroll
                    for (int nt = 0; nt < 4; nt++) {
                        const uint32_t* bh = (nt >> 1) ? bh1 : bh0;
                        const uint32_t* bl = (nt >> 1) ? bl1 : bl0;
                        int s = nt & 1;
                        float* d = d1 + (mt * 4 + nt) * 4;
                        mma16816(d, ah, bh[s], bh[s + 2]);
                        mma16816(d, ah, bl[s], bl[s + 2]);
                        mma16816(d, al, bh[s], bh[s + 2]);
                    }
                }
            }
            // pass 2: d2 += V.Q
            {
                uint32_t ah0[4], ah1[4], al0[4], al1[4];
                ldsm4(ah0, abase + 2 * 8192 + paddr(arow, colb));
                ldsm4(ah1, abase + 2 * 8192 + paddr(arow + 16, colb));
                ldsm4(al0, abase + 3 * 8192 + paddr(arow, colb));
                ldsm4(al1, abase + 3 * 8192 + paddr(arow + 16, colb));
                uint32_t bh0[4], bh1[4], bl0[4], bl1[4];
                uint32_t b2 = sb + FS_B + 2 * 32768 + ch * 4096;
                uint32_t b3 = sb + FS_B + 3 * 32768 + ch * 4096;
                ldsm4(bh0, b2 + paddr(brow, colb));
                ldsm4(bh1, b2 + paddr(brow + 16, colb));
                ldsm4(bl0, b3 + paddr(brow, colb));
                ldsm4(bl1, b3 + paddr(brow + 16, colb));
                #pragma unroll
                for (int mt = 0; mt < 2; mt++) {
                    const uint32_t* ah = mt ? ah1 : ah0;
                    const uint32_t* al = mt ? al1 : al0;
                    #pragma unroll
                    for (int nt = 0; nt < 4; nt++) {
                        const uint32_t* bh = (nt >> 1) ? bh1 : bh0;
                        const uint32_t* bl = (nt >> 1) ? bl1 : bl0;
                        int s = nt & 1;
                        float* d = d2 + (mt * 4 + nt) * 4;
                        mma16816(d, ah, bh[s], bh[s + 2]);
                        mma16816(d, ah, bl[s], bl[s + 2]);
                        mma16816(d, al, bh[s], bh[s + 2]);
                    }
                }
            }
        }
        if (ch == 7) {
            #pragma unroll
            for (int i = 0; i < 32; i++) {
                f[i] += d1[i] * d2[i];
                d1[i] = 0.f; d2[i] = 0.f;
            }
        }
        __syncthreads();
    }

    // ---- epilogue ----
    int r4 = lane >> 2, c2 = (lane & 3) * 2;
    #pragma unroll
    for (int mt = 0; mt < 2; mt++) {
        #pragma unroll
        for (int nt = 0; nt < 4; nt++) {
            float* d = f + (mt * 4 + nt) * 4;
            long row = i0 + wi * 32 + mt * 16 + r4;
            long col = j0 + wj * 32 + nt * 8 + c2;
            float* dst = F + ((long)b * T_ + row) * T_ + col;
            dst[0] = d[0]; dst[1] = d[1];
            dst[8 * T_] = d[2]; dst[8 * T_ + 1] = d[3];
        }
    }
}

// ---------------- fused M + d kernel ----------------
__global__ void md_kernel(const float* __restrict__ Bias, const float* __restrict__ Mul,
                          const float* __restrict__ F, const float* __restrict__ w,
                          const float* __restrict__ pad, float* __restrict__ d) {
    int b  = blockIdx.y;
    int c0 = blockIdx.x * 64;
    __shared__ float Ms[16][68];
    __shared__ float Fs[16][68];
    __shared__ float red[16][64];
    int tid = threadIdx.x;
    int tx = tid & 15, ty = tid >> 4;
    float acc[4][4] = {};
    const float* Mb = Mul + (long)b * G_ * T_;
    const float* Fb = F   + (long)b * T_ * T_;
    for (int i0 = 0; i0 < T_; i0 += 16) {
        #pragma unroll
        for (int p = 0; p < 4; p++) {
            int r = (tid >> 4) + p * 16;
            int c = tid & 15;
            Ms[c][r] = Mb[r * T_ + i0 + c];
        }
        #pragma unroll
        for (int p = 0; p < 4; p++) {
            int r = (tid >> 6) + p * 4;
            int c = tid & 63;
            Fs[r][c] = Fb[(long)(i0 + r) * T_ + c0 + c];
        }
        __syncthreads();
        #pragma unroll
        for (int ii = 0; ii < 16; ii++) {
            float4 m4 = *reinterpret_cast<const float4*>(&Ms[ii][ty * 4]);
            float m[4] = {m4.x, m4.y, m4.z, m4.w};
            float4 f4 = *reinterpret_cast<const float4*>(&Fs[ii][tx * 4]);
            float ff[4] = {f4.x, f4.y, f4.z, f4.w};
            #pragma unroll
            for (int i = 0; i < 4; i++)
                #pragma unroll
                for (int j = 0; j < 4; j++)
                    acc[i][j] += m[i] * ff[j];
        }
        __syncthreads();
    }
    float part[4] = {0.f, 0.f, 0.f, 0.f};
    #pragma unroll
    for (int gq = 0; gq < 4; gq++) {
        int g = ty * 4 + gq;
        float wg = w[g];
        #pragma unroll
        for (int c = 0; c < 4; c++) {
            float vv = acc[gq][c] + Bias[(long)b * G_ * T_ + g * T_ + c0 + tx * 4 + c];
            part[c] += wg * fmaxf(vv, 0.f);
        }
    }
    #pragma unroll
    for (int c = 0; c < 4; c++) red[ty][tx * 4 + c] = part[c];
    __syncthreads();
    #pragma unroll
    for (int s = 8; s > 0; s >>= 1) {
        if (ty < s) {
            #pragma unroll
            for (int c = 0; c < 4; c++) red[ty][tx * 4 + c] += red[ty + s][tx * 4 + c];
        }
        __syncthreads();
    }
    if (ty == 0) {
        #pragma unroll
        for (int c = 0; c < 4; c++) {
            int col = c0 + tx * 4 + c;
            d[b * T_ + col] = red[0][tx * 4 + c] - NEGC * pad[b * T_ + col];
        }
    }
}

// ---------------- softmax ----------------
__global__ void softmax_kernel(const float* __restrict__ d1, const float* __restrict__ d2,
                               float* __restrict__ g1, float* __restrict__ g2) {
    int b = blockIdx.x;
    const float* d = blockIdx.y ? d2 : d1;
    float* g = blockIdx.y ? g2 : g1;
    int t = threadIdx.x;
    float v = d[b * T_ + t];
    __shared__ float red[16];
    float m = v;
    #pragma unroll
    for (int o = 16; o; o >>= 1) m = fmaxf(m, __shfl_xor_sync(0xffffffffu, m, o));
    if ((t & 31) == 0) red[t >> 5] = m;
    __syncthreads();
    if (t < 32) {
        float x = (t < 16) ? red[t] : -3.4e38f;
        #pragma unroll
        for (int o = 8; o; o >>= 1) x = fmaxf(x, __shfl_xor_sync(0xffffffffu, x, o));
        if (t == 0) red[0] = x;
    }
    __syncthreads();
    float mx = red[0];
    __syncthreads();
    float e = expf(v - mx);
    float s = e;
    #pragma unroll
    for (int o = 16; o; o >>= 1) s += __shfl_xor_sync(0xffffffffu, s, o);
    if ((t & 31) == 0) red[t >> 5] = s;
    __syncthreads();
    if (t < 32) {
        float x = (t < 16) ? red[t] : 0.f;
        #pragma unroll
        for (int o = 8; o; o >>= 1) x += __shfl_xor_sync(0xffffffffu, x, o);
        if (t == 0) red[0] = x;
    }
    __syncthreads();
    g[b * T_ + t] = e / red[0];
}

// ---------------- final reduction ----------------
__global__ void final_kernel(const float* __restrict__ R, const float* __restrict__ Q,
                             const float* __restrict__ gv, const float* __restrict__ gq,
                             float* __restrict__ out) {
    int b = blockIdx.x;
    __shared__ float sgv[T_], sgq[T_];
    int tid = threadIdx.x;
    sgv[tid] = gv[b * T_ + tid];
    sgq[tid] = gq[b * T_ + tid];
    __syncthreads();
    int o = tid & 255;
    int h = tid >> 8;
    const float* Rb = R + (long)b * O_ * T_;
    const float* Qb = Q + (long)b * O_ * T_;
    float tr = 0.f, lg = 0.f;
    #pragma unroll 4
    for (int t = h * 256; t < h * 256 + 256; t++) {
        tr += sgv[t] * Rb[t * O_ + o];
        lg += sgq[t] * Qb[t * O_ + o];
    }
    __shared__ float str[2][256], slg[2][256];
    str[h][o] = tr;
    slg[h][o] = lg;
    __syncthreads();
    if (h == 0) out[b * O_ + o] = (str[0][o] + str[1][o]) * (slg[0][o] + slg[1][o]);
}

// ---------------- launcher ----------------
extern "C" void kernel_launch(void* const* d_in, const int* in_sizes, int n_in,
                              void* d_out, int out_size) {
    const float* x0  = (const float*)d_in[0];
    const float* x1  = (const float*)d_in[1];
    const unsigned char* qm = (const unsigned char*)d_in[2];
    const unsigned char* vm = (const unsigned char*)d_in[3];
    const float* W_R = (const float*)d_in[4];
    const float* W_Q = (const float*)d_in[5];
    const float* br  = (const float*)d_in[6];
    const float* bq  = (const float*)d_in[7];
    const float* U   = (const float*)d_in[8];
    const float* V   = (const float*)d_in[9];
    const float* W2R = (const float*)d_in[10];
    const float* W2Q = (const float*)d_in[11];
    const float* wmv = (const float*)d_in[12];
    const float* wmq = (const float*)d_in[13];
    float* out = (float*)d_out;

    float *pR, *pQ, *pF, *pWR, *pWQ, *pd1, *pd2, *pg1, *pg2, *ppq, *ppv;
    __nv_bfloat16 *pUh, *pUl, *pVh, *pVl, *pRh, *pRl, *pQh, *pQl;
    cudaGetSymbolAddress((void**)&pR,  g_R);
    cudaGetSymbolAddress((void**)&pQ,  g_Q);
    cudaGetSymbolAddress((void**)&pF,  g_F);
    cudaGetSymbolAddress((void**)&pWR, g_WR);
    cudaGetSymbolAddress((void**)&pWQ, g_WQ);
    cudaGetSymbolAddress((void**)&pd1, g_d1);
    cudaGetSymbolAddress((void**)&pd2, g_d2);
    cudaGetSymbolAddress((void**)&pg1, g_g1);
    cudaGetSymbolAddress((void**)&pg2, g_g2);
    cudaGetSymbolAddress((void**)&ppq, g_pq);
    cudaGetSymbolAddress((void**)&ppv, g_pv);
    cudaGetSymbolAddress((void**)&pUh, g_Ukh);
    cudaGetSymbolAddress((void**)&pUl, g_Ukl);
    cudaGetSymbolAddress((void**)&pVh, g_Vkh);
    cudaGetSymbolAddress((void**)&pVl, g_Vkl);
    cudaGetSymbolAddress((void**)&pRh, g_Rth);
    cudaGetSymbolAddress((void**)&pRl, g_Rtl);
    cudaGetSymbolAddress((void**)&pQh, g_Qth);
    cudaGetSymbolAddress((void**)&pQl, g_Qtl);

    static bool attr_done = false;
    if (!attr_done) {
        cudaFuncSetAttribute(f_mma_kernel, cudaFuncAttributeMaxDynamicSharedMemorySize, FS_TOTAL);
        attr_done = true;
    }

    maskconv_kernel<<<(B_ * T_ + 255) / 256, 256>>>(qm, vm, ppq, ppv);
    convUV_kernel<<<(KF_ * T_ * O_ + 255) / 256, 256>>>(U, V, pUh, pUl, pVh, pVl);

    gemm64_kernel<true><<<dim3(T_ / 64, O_ / 64, B_), 256>>>(
        W_R, x0, pR, D_, T_, O_, (long)D_ * T_, br, ppq);
    gemm64_kernel<true><<<dim3(T_ / 64, O_ / 64, B_), 256>>>(
        W_Q, x1, pQ, D_, T_, O_, (long)D_ * T_, bq, ppv);

    convRQ_kernel<<<dim3(T_ / 32, O_ / 32, 2 * B_), dim3(32, 8)>>>(
        pR, pQ, pRh, pRl, pQh, pQl);

    f_mma_kernel<<<dim3(T_ / 64, T_ / 128, B_), 256, FS_TOTAL>>>(
        pUh, pUl, pVh, pVl, pRh, pRl, pQh, pQl, pF);

    gemm64_kernel<false><<<dim3(T_ / 64, 1, B_), 256>>>(
        W2R, pR, pWR, O_, T_, G_, (long)O_ * T_, nullptr, nullptr);
    gemm64_kernel<false><<<dim3(T_ / 64, 1, B_), 256>>>(
        W2Q, pQ, pWQ, O_, T_, G_, (long)O_ * T_, nullptr, nullptr);

    md_kernel<<<dim3(T_ / 64, B_), 256>>>(pWR, pWQ, pF, wmv, ppq, pd1);
    md_kernel<<<dim3(T_ / 64, B_), 256>>>(pWQ, pWR, pF, wmq, ppv, pd2);

    softmax_kernel<<<dim3(B_, 2), T_>>>(pd1, pd2, pg1, pg2);

    final_kernel<<<B_, T_>>>(pR, pQ, pg1, pg2, out);
}

// round 6
// speedup vs baseline: 2.8537x; 1.2456x over previous
#include <cuda_runtime.h>
#include <cuda_bf16.h>
#include <cstdint>

#define NEGC 1e9f

#define B_  32
#define T_  512
#define D_  256
#define O_  256
#define KF_ 8
#define G_  64

// ---------------- scratch ----------------
__device__ float g_R [B_ * O_ * T_];
__device__ float g_Q [B_ * O_ * T_];
__device__ float g_F [B_ * T_ * T_];
__device__ float g_WR[B_ * G_ * T_];
__device__ float g_WQ[B_ * G_ * T_];
__device__ float g_d1[B_ * T_];
__device__ float g_d2[B_ * T_];
__device__ float g_g1[B_ * T_];
__device__ float g_g2[B_ * T_];
__device__ float g_pq[B_ * T_];
__device__ float g_pv[B_ * T_];
__device__ int   g_len1[B_];
__device__ int   g_len2[B_];
__device__ int   g_jmin[B_];

__device__ __nv_bfloat16 g_Ukh[KF_ * T_ * O_];
__device__ __nv_bfloat16 g_Ukl[KF_ * T_ * O_];
__device__ __nv_bfloat16 g_Vkh[KF_ * T_ * O_];
__device__ __nv_bfloat16 g_Vkl[KF_ * T_ * O_];
__device__ __nv_bfloat16 g_Rth[B_ * T_ * O_];
__device__ __nv_bfloat16 g_Rtl[B_ * T_ * O_];
__device__ __nv_bfloat16 g_Qth[B_ * T_ * O_];
__device__ __nv_bfloat16 g_Qtl[B_ * T_ * O_];

// =================== helpers ===================
__device__ __forceinline__ uint32_t smem_to_u32(const void* p) {
    uint32_t a;
    asm("{ .reg .u64 t; cvta.to.shared.u64 t, %1; cvt.u32.u64 %0, t; }" : "=r"(a) : "l"(p));
    return a;
}
__device__ __forceinline__ void ldsm4(uint32_t* r, uint32_t addr) {
    asm volatile("ldmatrix.sync.aligned.m8n8.x4.shared.b16 {%0,%1,%2,%3}, [%4];"
        : "=r"(r[0]), "=r"(r[1]), "=r"(r[2]), "=r"(r[3]) : "r"(addr));
}
__device__ __forceinline__ void mma16816(float* d, const uint32_t* a,
                                         uint32_t b0, uint32_t b1) {
    asm volatile("mma.sync.aligned.m16n8k16.row.col.f32.bf16.bf16.f32 "
        "{%0,%1,%2,%3}, {%4,%5,%6,%7}, {%8,%9}, {%0,%1,%2,%3};"
        : "+f"(d[0]), "+f"(d[1]), "+f"(d[2]), "+f"(d[3])
        : "r"(a[0]), "r"(a[1]), "r"(a[2]), "r"(a[3]), "r"(b0), "r"(b1));
}
__device__ __forceinline__ void cpasync16(uint32_t dst, const void* src) {
    asm volatile("cp.async.cg.shared.global [%0], [%1], 16;" :: "r"(dst), "l"(src));
}
#define CP_COMMIT() asm volatile("cp.async.commit_group;" ::: "memory")
#define CP_WAIT(n)  asm volatile("cp.async.wait_group %0;" :: "n"(n) : "memory")

__device__ __forceinline__ uint32_t paddr(uint32_t row, uint32_t cb) {
    uint32_t pr = row >> 1;
    return pr * 128 + ((((row & 1) << 6) + cb) ^ ((pr & 7) << 4));
}

// mask dtype decode shared logic
__device__ __forceinline__ void decode_mask(const unsigned char* q, const unsigned char* v,
                                            int i, bool& qv, bool& vv) {
    unsigned char b1 = q[1], b3 = q[3];
    int type = (b1 == 1) ? 0 : (b1 == 0x3F) ? 3 : (b3 == 0x3F) ? 2 : 1;
    switch (type) {
        case 0: qv = q[i] != 0;                            vv = v[i] != 0; break;
        case 1: qv = ((const int*)q)[i] != 0;              vv = ((const int*)v)[i] != 0; break;
        case 2: qv = ((const float*)q)[i] != 0.f;          vv = ((const float*)v)[i] != 0.f; break;
        default: qv = ((const unsigned short*)q)[i] != 0;  vv = ((const unsigned short*)v)[i] != 0; break;
    }
}

// ---------------- mask decode ----------------
__global__ void maskconv_kernel(const unsigned char* __restrict__ q,
                                const unsigned char* __restrict__ v,
                                float* __restrict__ pq, float* __restrict__ pv) {
    int i = blockIdx.x * blockDim.x + threadIdx.x;
    if (i >= B_ * T_) return;
    bool qv, vv;
    decode_mask(q, v, i, qv, vv);
    pq[i] = qv ? 0.f : 1.f;
    pv[i] = vv ? 0.f : 1.f;
}

// ---------------- per-batch valid lengths ----------------
__global__ void lens_kernel(const unsigned char* __restrict__ q,
                            const unsigned char* __restrict__ v,
                            int* __restrict__ len1, int* __restrict__ len2,
                            int* __restrict__ jmin) {
    __shared__ int s1, s2;
    int b = blockIdx.x, t = threadIdx.x;   // 512 threads
    if (t == 0) { s1 = 0; s2 = 0; }
    __syncthreads();
    bool qv, vv;
    decode_mask(q, v, b * T_ + t, qv, vv);
    unsigned m1 = __ballot_sync(0xffffffffu, qv);
    unsigned m2 = __ballot_sync(0xffffffffu, vv);
    if ((t & 31) == 0) { atomicAdd(&s1, __popc(m1)); atomicAdd(&s2, __popc(m2)); }
    __syncthreads();
    if (t == 0) {
        len1[b] = s1; len2[b] = s2;
        jmin[b] = s1 < s2 ? s1 : s2;
    }
}

// ---------------- U/V de-interleave + bf16 split ----------------
__global__ void convUV_kernel(const float* __restrict__ U, const float* __restrict__ V,
                              __nv_bfloat16* __restrict__ Uh, __nv_bfloat16* __restrict__ Ul,
                              __nv_bfloat16* __restrict__ Vh, __nv_bfloat16* __restrict__ Vl) {
    int idx = blockIdx.x * blockDim.x + threadIdx.x;
    if (idx >= KF_ * T_ * O_) return;
    int k = idx >> 17;
    int m = idx & (T_ * O_ - 1);
    float u = U[m * KF_ + k];
    float v = V[m * KF_ + k];
    __nv_bfloat16 uh = __float2bfloat16(u);
    __nv_bfloat16 vh = __float2bfloat16(v);
    Uh[idx] = uh; Ul[idx] = __float2bfloat16(u - __bfloat162float(uh));
    Vh[idx] = vh; Vl[idx] = __float2bfloat16(v - __bfloat162float(vh));
}

// ---------------- transpose + bf16 split ----------------
__global__ void convRQ_kernel(const float* __restrict__ R, const float* __restrict__ Q,
                              __nv_bfloat16* __restrict__ Rh, __nv_bfloat16* __restrict__ Rl,
                              __nv_bfloat16* __restrict__ Qh, __nv_bfloat16* __restrict__ Ql) {
    __shared__ float tile[32][33];
    int zz = blockIdx.z;
    int b = zz & 31;
    bool isQ = (zz >> 5) != 0;
    const float* src = (isQ ? Q : R) + (long)b * O_ * T_;
    __nv_bfloat16* dh = (isQ ? Qh : Rh) + (long)b * T_ * O_;
    __nv_bfloat16* dl = (isQ ? Ql : Rl) + (long)b * T_ * O_;
    int t0 = blockIdx.x * 32, o0 = blockIdx.y * 32;
    int tx = threadIdx.x, ty = threadIdx.y;
    #pragma unroll
    for (int r = 0; r < 4; r++)
        tile[ty + r * 8][tx] = src[(long)(o0 + ty + r * 8) * T_ + t0 + tx];
    __syncthreads();
    #pragma unroll
    for (int r = 0; r < 4; r++) {
        int t = t0 + ty + r * 8;
        float v = tile[tx][ty + r * 8];
        __nv_bfloat16 h = __float2bfloat16(v);
        dh[(long)t * O_ + o0 + tx] = h;
        dl[(long)t * O_ + o0 + tx] = __float2bfloat16(v - __bfloat162float(h));
    }
}

// ---------------- R/Q GEMM: 64(m)x128(n) tile, 128 thr, 8x8/thread ----------------
// C[b,m,n] = relu(sum_k A[m,k]*x[b,k,n] - NEG*pad[b,n] + bias[m]);  K=D_, N=T_, M=O_
__global__ __launch_bounds__(128) void gemm_rq_kernel(
    const float* __restrict__ A, const float* __restrict__ Bm,
    float* __restrict__ C, const float* __restrict__ bias,
    const float* __restrict__ pad) {
    int b = blockIdx.z;
    int n0 = blockIdx.x * 128;
    int m0 = blockIdx.y * 64;
    const float* Bb = Bm + (long)b * (D_ * T_);
    __shared__ float As[16][68];
    __shared__ float Bs[16][132];
    int tid = threadIdx.x;
    int tx = tid & 15, ty = tid >> 4;
    float acc[8][8] = {};
    for (int k0 = 0; k0 < D_; k0 += 16) {
        #pragma unroll
        for (int e = 0; e < 2; e++) {
            int idx = tid + e * 128;
            int m = idx >> 2, kq = idx & 3;
            float4 a = *reinterpret_cast<const float4*>(&A[(m0 + m) * D_ + k0 + kq * 4]);
            As[kq * 4 + 0][m] = a.x; As[kq * 4 + 1][m] = a.y;
            As[kq * 4 + 2][m] = a.z; As[kq * 4 + 3][m] = a.w;
        }
        #pragma unroll
        for (int e = 0; e < 4; e++) {
            int idx = tid + e * 128;
            int r = idx >> 5, cq = idx & 31;
            *reinterpret_cast<float4*>(&Bs[r][cq * 4]) =
                *reinterpret_cast<const float4*>(&Bb[(long)(k0 + r) * T_ + n0 + cq * 4]);
        }
        __syncthreads();
        #pragma unroll
        for (int kk = 0; kk < 16; kk++) {
            float4 a0 = *reinterpret_cast<const float4*>(&As[kk][ty * 8]);
            float4 a1 = *reinterpret_cast<const float4*>(&As[kk][ty * 8 + 4]);
            float4 b0 = *reinterpret_cast<const float4*>(&Bs[kk][tx * 8]);
            float4 b1 = *reinterpret_cast<const float4*>(&Bs[kk][tx * 8 + 4]);
            float av[8] = {a0.x, a0.y, a0.z, a0.w, a1.x, a1.y, a1.z, a1.w};
            float bv[8] = {b0.x, b0.y, b0.z, b0.w, b1.x, b1.y, b1.z, b1.w};
            #pragma unroll
            for (int i = 0; i < 8; i++)
                #pragma unroll
                for (int j = 0; j < 8; j++)
                    acc[i][j] += av[i] * bv[j];
        }
        __syncthreads();
    }
    #pragma unroll
    for (int i = 0; i < 8; i++) {
        int m = m0 + ty * 8 + i;
        float bi = bias[m];
        #pragma unroll
        for (int j = 0; j < 8; j++) {
            int n = n0 + tx * 8 + j;
            acc[i][j] = fmaxf(acc[i][j] - NEGC * pad[b * T_ + n] + bi, 0.f);
        }
        float* dst = &C[((long)b * O_ + m) * T_ + n0 + tx * 8];
        *reinterpret_cast<float4*>(dst) = make_float4(acc[i][0], acc[i][1], acc[i][2], acc[i][3]);
        *reinterpret_cast<float4*>(dst + 4) = make_float4(acc[i][4], acc[i][5], acc[i][6], acc[i][7]);
    }
}

// ---------------- generic 64x64 tile GEMM (W2 only) ----------------
__global__ void gemm64_kernel(const float* __restrict__ A, const float* __restrict__ Bm,
                              float* __restrict__ C, int K, int N, int Mtot,
                              long strideB) {
    int b  = blockIdx.z;
    int n0 = blockIdx.x * 64;
    int m0 = blockIdx.y * 64;
    const float* Bb = Bm + (long)b * strideB;
    __shared__ float As[16][68];
    __shared__ float Bs[16][68];
    int tid = threadIdx.x;
    int tx = tid & 15, ty = tid >> 4;
    float acc[4][4] = {};
    for (int k0 = 0; k0 < K; k0 += 16) {
        #pragma unroll
        for (int p = 0; p < 4; p++) {
            int r = (tid >> 4) + p * 16;
            int c = tid & 15;
            As[c][r] = A[(m0 + r) * K + k0 + c];
        }
        #pragma unroll
        for (int p = 0; p < 4; p++) {
            int r = (tid >> 6) + p * 4;
            int c = tid & 63;
            Bs[r][c] = Bb[(long)(k0 + r) * N + n0 + c];
        }
        __syncthreads();
        #pragma unroll
        for (int kk = 0; kk < 16; kk++) {
            float4 a4 = *reinterpret_cast<const float4*>(&As[kk][ty * 4]);
            float a[4] = {a4.x, a4.y, a4.z, a4.w};
            float4 bb = *reinterpret_cast<const float4*>(&Bs[kk][tx * 4]);
            float bv[4] = {bb.x, bb.y, bb.z, bb.w};
            #pragma unroll
            for (int i = 0; i < 4; i++)
                #pragma unroll
                for (int j = 0; j < 4; j++)
                    acc[i][j] += a[i] * bv[j];
        }
        __syncthreads();
    }
    #pragma unroll
    for (int i = 0; i < 4; i++) {
        int m = m0 + ty * 4 + i;
        #pragma unroll
        for (int j = 0; j < 4; j++) {
            int n = n0 + tx * 4 + j;
            C[(long)b * Mtot * N + (long)m * N + n] = acc[i][j];
        }
    }
}

// ======================= HMMA F kernel (with j-tile skip) =======================
#define FS_B 65536
#define FS_TOTAL 196608

__global__ __launch_bounds__(256, 1) void f_mma_kernel(
    const __nv_bfloat16* __restrict__ Uh, const __nv_bfloat16* __restrict__ Ul,
    const __nv_bfloat16* __restrict__ Vh, const __nv_bfloat16* __restrict__ Vl,
    const __nv_bfloat16* __restrict__ Rh, const __nv_bfloat16* __restrict__ Rl,
    const __nv_bfloat16* __restrict__ Qh, const __nv_bfloat16* __restrict__ Ql,
    float* __restrict__ F, const int* __restrict__ jmin) {
    extern __shared__ char sm[];
    uint32_t sb = smem_to_u32(sm);
    int tid = threadIdx.x, lane = tid & 31, w = tid >> 5;
    int wi = w >> 1, wj = w & 1;
    int b = blockIdx.z, i0 = blockIdx.y * 128, j0 = blockIdx.x * 64;
    int l16 = lane & 15, lh = lane >> 4;

    // ---- early-out: fully masked j-tile -> F is exactly zero ----
    if (j0 >= jmin[b]) {
        int row = tid >> 1, half = tid & 1;
        float4 z = make_float4(0.f, 0.f, 0.f, 0.f);
        float* dst = F + ((long)b * T_ + i0 + row) * T_ + j0 + half * 32;
        #pragma unroll
        for (int e = 0; e < 8; e++) reinterpret_cast<float4*>(dst)[e] = z;
        return;
    }

    const __nv_bfloat16* apt[4] = {Uh, Ul, Vh, Vl};
    const __nv_bfloat16* bpt[4] = {Rh, Rl, Qh, Ql};

    #pragma unroll
    for (int arr = 0; arr < 4; arr++) {
        const __nv_bfloat16* src = bpt[arr] + ((long)b * T_ + j0) * O_;
        #pragma unroll
        for (int e = 0; e < 8; e++) {
            int idx = tid + e * 256;
            int ch = idx >> 8;
            int row = (idx & 255) >> 2;
            int cb = (idx & 3) * 16;
            const void* g = src + (long)row * O_ + ch * 32 + cb / 2;
            cpasync16(sb + FS_B + arr * 32768 + ch * 4096 + paddr(row, cb), g);
        }
    }
    CP_COMMIT();

    auto load_a = [&](int cu, int st) {
        int k = cu >> 3, ch = cu & 7;
        #pragma unroll
        for (int arr = 0; arr < 4; arr++) {
            const __nv_bfloat16* src = apt[arr] + ((long)k * T_ + i0) * O_ + ch * 32;
            #pragma unroll
            for (int e = 0; e < 2; e++) {
                int idx = tid + e * 256;
                int row = idx >> 2;
                int cb = (idx & 3) * 16;
                const void* g = src + (long)row * O_ + cb / 2;
                cpasync16(sb + st * 32768 + arr * 8192 + paddr(row, cb), g);
            }
        }
    };

    load_a(0, 0);
    CP_COMMIT();

    float f[32], d1[32], d2[32];
    #pragma unroll
    for (int i = 0; i < 32; i++) { f[i] = 0.f; d1[i] = 0.f; d2[i] = 0.f; }

    for (int cu = 0; cu < 64; cu++) {
        int st = cu & 1, ch = cu & 7;
        if (cu + 1 < 64) {
            load_a(cu + 1, (cu + 1) & 1);
            CP_COMMIT();
            CP_WAIT(1);
        } else {
            CP_WAIT(0);
        }
        __syncthreads();

        uint32_t abase = sb + st * 32768;
        #pragma unroll
        for (int os = 0; os < 2; os++) {
            uint32_t colb = (uint32_t)(os * 32 + lh * 16);
            uint32_t arow = (uint32_t)(wi * 32 + l16);
            uint32_t brow = (uint32_t)(wj * 32 + l16);
            {
                uint32_t ah0[4], ah1[4], al0[4], al1[4];
                ldsm4(ah0, abase + 0 * 8192 + paddr(arow, colb));
                ldsm4(ah1, abase + 0 * 8192 + paddr(arow + 16, colb));
                ldsm4(al0, abase + 1 * 8192 + paddr(arow, colb));
                ldsm4(al1, abase + 1 * 8192 + paddr(arow + 16, colb));
                uint32_t bh0[4], bh1[4], bl0[4], bl1[4];
                uint32_t b0 = sb + FS_B + 0 * 32768 + ch * 4096;
                uint32_t b1 = sb + FS_B + 1 * 32768 + ch * 4096;
                ldsm4(bh0, b0 + paddr(brow, colb));
                ldsm4(bh1, b0 + paddr(brow + 16, colb));
                ldsm4(bl0, b1 + paddr(brow, colb));
                ldsm4(bl1, b1 + paddr(brow + 16, colb));
                #pragma unroll
                for (int mt = 0; mt < 2; mt++) {
                    const uint32_t* ah = mt ? ah1 : ah0;
                    const uint32_t* al = mt ? al1 : al0;
                    #pragma unroll
                    for (int nt = 0; nt < 4; nt++) {
                        const uint32_t* bh = (nt >> 1) ? bh1 : bh0;
                        const uint32_t* bl = (nt >> 1) ? bl1 : bl0;
                        int s = nt & 1;
                        float* d = d1 + (mt * 4 + nt) * 4;
                        mma16816(d, ah, bh[s], bh[s + 2]);
                        mma16816(d, ah, bl[s], bl[s + 2]);
                        mma16816(d, al, bh[s], bh[s + 2]);
                    }
                }
            }
            {
                uint32_t ah0[4], ah1[4], al0[4], al1[4];
                ldsm4(ah0, abase + 2 * 8192 + paddr(arow, colb));
                ldsm4(ah1, abase + 2 * 8192 + paddr(arow + 16, colb));
                ldsm4(al0, abase + 3 * 8192 + paddr(arow, colb));
                ldsm4(al1, abase + 3 * 8192 + paddr(arow + 16, colb));
                uint32_t bh0[4], bh1[4], bl0[4], bl1[4];
                uint32_t b2 = sb + FS_B + 2 * 32768 + ch * 4096;
                uint32_t b3 = sb + FS_B + 3 * 32768 + ch * 4096;
                ldsm4(bh0, b2 + paddr(brow, colb));
                ldsm4(bh1, b2 + paddr(brow + 16, colb));
                ldsm4(bl0, b3 + paddr(brow, colb));
                ldsm4(bl1, b3 + paddr(brow + 16, colb));
                #pragma unroll
                for (int mt = 0; mt < 2; mt++) {
                    const uint32_t* ah = mt ? ah1 : ah0;
                    const uint32_t* al = mt ? al1 : al0;
                    #pragma unroll
                    for (int nt = 0; nt < 4; nt++) {
                        const uint32_t* bh = (nt >> 1) ? bh1 : bh0;
                        const uint32_t* bl = (nt >> 1) ? bl1 : bl0;
                        int s = nt & 1;
                        float* d = d2 + (mt * 4 + nt) * 4;
                        mma16816(d, ah, bh[s], bh[s + 2]);
                        mma16816(d, ah, bl[s], bl[s + 2]);
                        mma16816(d, al, bh[s], bh[s + 2]);
                    }
                }
            }
        }
        if (ch == 7) {
            #pragma unroll
            for (int i = 0; i < 32; i++) {
                f[i] += d1[i] * d2[i];
                d1[i] = 0.f; d2[i] = 0.f;
            }
        }
        __syncthreads();
    }

    int r4 = lane >> 2, c2 = (lane & 3) * 2;
    #pragma unroll
    for (int mt = 0; mt < 2; mt++) {
        #pragma unroll
        for (int nt = 0; nt < 4; nt++) {
            float* d = f + (mt * 4 + nt) * 4;
            long row = i0 + wi * 32 + mt * 16 + r4;
            long col = j0 + wj * 32 + nt * 8 + c2;
            float* dst = F + ((long)b * T_ + row) * T_ + col;
            dst[0] = d[0]; dst[1] = d[1];
            dst[8 * T_] = d[2]; dst[8 * T_ + 1] = d[3];
        }
    }
}

// ---------------- fused M + d kernel (with col-tile skip) ----------------
__global__ void md_kernel(const float* __restrict__ Bias, const float* __restrict__ Mul,
                          const float* __restrict__ F, const float* __restrict__ w,
                          const float* __restrict__ pad, float* __restrict__ d,
                          const int* __restrict__ lenp) {
    int b  = blockIdx.y;
    int c0 = blockIdx.x * 64;
    int tid = threadIdx.x;
    if (c0 >= lenp[b]) {
        // masked cols: softmax arg underflows to exactly 0 either way
        if (tid < 64) d[b * T_ + c0 + tid] = -NEGC;
        return;
    }
    __shared__ float Ms[16][68];
    __shared__ float Fs[16][68];
    __shared__ float red[16][64];
    int tx = tid & 15, ty = tid >> 4;
    float acc[4][4] = {};
    const float* Mb = Mul + (long)b * G_ * T_;
    const float* Fb = F   + (long)b * T_ * T_;
    for (int i0 = 0; i0 < T_; i0 += 16) {
        #pragma unroll
        for (int p = 0; p < 4; p++) {
            int r = (tid >> 4) + p * 16;
            int c = tid & 15;
            Ms[c][r] = Mb[r * T_ + i0 + c];
        }
        #pragma unroll
        for (int p = 0; p < 4; p++) {
            int r = (tid >> 6) + p * 4;
            int c = tid & 63;
            Fs[r][c] = Fb[(long)(i0 + r) * T_ + c0 + c];
        }
        __syncthreads();
        #pragma unroll
        for (int ii = 0; ii < 16; ii++) {
            float4 m4 = *reinterpret_cast<const float4*>(&Ms[ii][ty * 4]);
            float m[4] = {m4.x, m4.y, m4.z, m4.w};
            float4 f4 = *reinterpret_cast<const float4*>(&Fs[ii][tx * 4]);
            float ff[4] = {f4.x, f4.y, f4.z, f4.w};
            #pragma unroll
            for (int i = 0; i < 4; i++)
                #pragma unroll
                for (int j = 0; j < 4; j++)
                    acc[i][j] += m[i] * ff[j];
        }
        __syncthreads();
    }
    float part[4] = {0.f, 0.f, 0.f, 0.f};
    #pragma unroll
    for (int gq = 0; gq < 4; gq++) {
        int g = ty * 4 + gq;
        float wg = w[g];
        #pragma unroll
        for (int c = 0; c < 4; c++) {
            float vv = acc[gq][c] + Bias[(long)b * G_ * T_ + g * T_ + c0 + tx * 4 + c];
            part[c] += wg * fmaxf(vv, 0.f);
        }
    }
    #pragma unroll
    for (int c = 0; c < 4; c++) red[ty][tx * 4 + c] = part[c];
    __syncthreads();
    #pragma unroll
    for (int s = 8; s > 0; s >>= 1) {
        if (ty < s) {
            #pragma unroll
            for (int c = 0; c < 4; c++) red[ty][tx * 4 + c] += red[ty + s][tx * 4 + c];
        }
        __syncthreads();
    }
    if (ty == 0) {
        #pragma unroll
        for (int c = 0; c < 4; c++) {
            int col = c0 + tx * 4 + c;
            d[b * T_ + col] = red[0][tx * 4 + c] - NEGC * pad[b * T_ + col];
        }
    }
}

// ---------------- softmax ----------------
__global__ void softmax_kernel(const float* __restrict__ d1, const float* __restrict__ d2,
                               float* __restrict__ g1, float* __restrict__ g2) {
    int b = blockIdx.x;
    const float* d = blockIdx.y ? d2 : d1;
    float* g = blockIdx.y ? g2 : g1;
    int t = threadIdx.x;
    float v = d[b * T_ + t];
    __shared__ float red[16];
    float m = v;
    #pragma unroll
    for (int o = 16; o; o >>= 1) m = fmaxf(m, __shfl_xor_sync(0xffffffffu, m, o));
    if ((t & 31) == 0) red[t >> 5] = m;
    __syncthreads();
    if (t < 32) {
        float x = (t < 16) ? red[t] : -3.4e38f;
        #pragma unroll
        for (int o = 8; o; o >>= 1) x = fmaxf(x, __shfl_xor_sync(0xffffffffu, x, o));
        if (t == 0) red[0] = x;
    }
    __syncthreads();
    float mx = red[0];
    __syncthreads();
    float e = expf(v - mx);
    float s = e;
    #pragma unroll
    for (int o = 16; o; o >>= 1) s += __shfl_xor_sync(0xffffffffu, s, o);
    if ((t & 31) == 0) red[t >> 5] = s;
    __syncthreads();
    if (t < 32) {
        float x = (t < 16) ? red[t] : 0.f;
        #pragma unroll
        for (int o = 8; o; o >>= 1) x += __shfl_xor_sync(0xffffffffu, x, o);
        if (t == 0) red[0] = x;
    }
    __syncthreads();
    g[b * T_ + t] = e / red[0];
}

// ---------------- final reduction ----------------
__global__ void final_kernel(const float* __restrict__ R, const float* __restrict__ Q,
                             const float* __restrict__ gv, const float* __restrict__ gq,
                             float* __restrict__ out) {
    int b = blockIdx.x;
    __shared__ float sgv[T_], sgq[T_];
    int tid = threadIdx.x;
    sgv[tid] = gv[b * T_ + tid];
    sgq[tid] = gq[b * T_ + tid];
    __syncthreads();
    int o = tid & 255;
    int h = tid >> 8;
    const float* Rb = R + (long)b * O_ * T_;
    const float* Qb = Q + (long)b * O_ * T_;
    float tr = 0.f, lg = 0.f;
    #pragma unroll 4
    for (int t = h * 256; t < h * 256 + 256; t++) {
        tr += sgv[t] * Rb[t * O_ + o];
        lg += sgq[t] * Qb[t * O_ + o];
    }
    __shared__ float str[2][256], slg[2][256];
    str[h][o] = tr;
    slg[h][o] = lg;
    __syncthreads();
    if (h == 0) out[b * O_ + o] = (str[0][o] + str[1][o]) * (slg[0][o] + slg[1][o]);
}

// ---------------- launcher ----------------
extern "C" void kernel_launch(void* const* d_in, const int* in_sizes, int n_in,
                              void* d_out, int out_size) {
    const float* x0  = (const float*)d_in[0];
    const float* x1  = (const float*)d_in[1];
    const unsigned char* qm = (const unsigned char*)d_in[2];
    const unsigned char* vm = (const unsigned char*)d_in[3];
    const float* W_R = (const float*)d_in[4];
    const float* W_Q = (const float*)d_in[5];
    const float* br  = (const float*)d_in[6];
    const float* bq  = (const float*)d_in[7];
    const float* U   = (const float*)d_in[8];
    const float* V   = (const float*)d_in[9];
    const float* W2R = (const float*)d_in[10];
    const float* W2Q = (const float*)d_in[11];
    const float* wmv = (const float*)d_in[12];
    const float* wmq = (const float*)d_in[13];
    float* out = (float*)d_out;

    float *pR, *pQ, *pF, *pWR, *pWQ, *pd1, *pd2, *pg1, *pg2, *ppq, *ppv;
    int *pl1, *pl2, *pjm;
    __nv_bfloat16 *pUh, *pUl, *pVh, *pVl, *pRh, *pRl, *pQh, *pQl;
    cudaGetSymbolAddress((void**)&pR,  g_R);
    cudaGetSymbolAddress((void**)&pQ,  g_Q);
    cudaGetSymbolAddress((void**)&pF,  g_F);
    cudaGetSymbolAddress((void**)&pWR, g_WR);
    cudaGetSymbolAddress((void**)&pWQ, g_WQ);
    cudaGetSymbolAddress((void**)&pd1, g_d1);
    cudaGetSymbolAddress((void**)&pd2, g_d2);
    cudaGetSymbolAddress((void**)&pg1, g_g1);
    cudaGetSymbolAddress((void**)&pg2, g_g2);
    cudaGetSymbolAddress((void**)&ppq, g_pq);
    cudaGetSymbolAddress((void**)&ppv, g_pv);
    cudaGetSymbolAddress((void**)&pl1, g_len1);
    cudaGetSymbolAddress((void**)&pl2, g_len2);
    cudaGetSymbolAddress((void**)&pjm, g_jmin);
    cudaGetSymbolAddress((void**)&pUh, g_Ukh);
    cudaGetSymbolAddress((void**)&pUl, g_Ukl);
    cudaGetSymbolAddress((void**)&pVh, g_Vkh);
    cudaGetSymbolAddress((void**)&pVl, g_Vkl);
    cudaGetSymbolAddress((void**)&pRh, g_Rth);
    cudaGetSymbolAddress((void**)&pRl, g_Rtl);
    cudaGetSymbolAddress((void**)&pQh, g_Qth);
    cudaGetSymbolAddress((void**)&pQl, g_Qtl);

    static bool attr_done = false;
    if (!attr_done) {
        cudaFuncSetAttribute(f_mma_kernel, cudaFuncAttributeMaxDynamicSharedMemorySize, FS_TOTAL);
        attr_done = true;
    }

    maskconv_kernel<<<(B_ * T_ + 255) / 256, 256>>>(qm, vm, ppq, ppv);
    lens_kernel<<<B_, T_>>>(qm, vm, pl1, pl2, pjm);
    convUV_kernel<<<(KF_ * T_ * O_ + 255) / 256, 256>>>(U, V, pUh, pUl, pVh, pVl);

    gemm_rq_kernel<<<dim3(T_ / 128, O_ / 64, B_), 128>>>(W_R, x0, pR, br, ppq);
    gemm_rq_kernel<<<dim3(T_ / 128, O_ / 64, B_), 128>>>(W_Q, x1, pQ, bq, ppv);

    convRQ_kernel<<<dim3(T_ / 32, O_ / 32, 2 * B_), dim3(32, 8)>>>(
        pR, pQ, pRh, pRl, pQh, pQl);

    f_mma_kernel<<<dim3(T_ / 64, T_ / 128, B_), 256, FS_TOTAL>>>(
        pUh, pUl, pVh, pVl, pRh, pRl, pQh, pQl, pF, pjm);

    gemm64_kernel<<<dim3(T_ / 64, 1, B_), 256>>>(
        W2R, pR, pWR, O_, T_, G_, (long)O_ * T_);
    gemm64_kernel<<<dim3(T_ / 64, 1, B_), 256>>>(
        W2Q, pQ, pWQ, O_, T_, G_, (long)O_ * T_);

    md_kernel<<<dim3(T_ / 64, B_), 256>>>(pWR, pWQ, pF, wmv, ppq, pd1, pl1);
    md_kernel<<<dim3(T_ / 64, B_), 256>>>(pWQ, pWR, pF, wmq, ppv, pd2, pl2);

    softmax_kernel<<<dim3(B_, 2), T_>>>(pd1, pd2, pg1, pg2);

    final_kernel<<<B_, T_>>>(pR, pQ, pg1, pg2, out);
}